// round 6
// baseline (speedup 1.0000x reference)
#include <cuda_runtime.h>
#include <math.h>

#define LNUM 4
#define DIM 256
#define NH 8
#define MLP 1024
#define BATCH 8
#define SEQ 1024
#define HID 2048            // NH * DIM
#define ROWS (BATCH*SEQ)    // 8192
#define BH (BATCH*NH)       // 64

// ---------------- scratch (device globals; no allocation allowed) ----------------
__device__ float g_h[ROWS*DIM];            // LN output (k-permuted)      8 MB
__device__ float g_q[BH*SEQ*DIM];          // q [b,h,n,d']                8 MB
__device__ float g_k[BH*SEQ*DIM];          // k [b,h,n,d']                8 MB
__device__ float g_v[BH*DIM*SEQ];          // v TRANSPOSED [b,h,d,n']     8 MB
__device__ float g_o[(size_t)ROWS*HID];    // attn out [b,n,(h d)']      64 MB
__device__ float g_m[ROWS*MLP];            // mlp hidden (permuted)      32 MB
// transposed + tf32-rounded + k-permuted weights
__device__ float g_qkvw[LNUM*DIM*3*HID];   // [l][6144][256']            25 MB
__device__ float g_projw[LNUM*HID*DIM];    // [l][256][2048']             8 MB
__device__ float g_w1[LNUM*DIM*MLP];       // [l][1024][256']             4 MB
__device__ float g_w2[LNUM*MLP*DIM];       // [l][256][1024']             4 MB

__device__ __forceinline__ float f2tf32(float x) {
    unsigned y;
    asm("cvt.rna.tf32.f32 %0, %1;" : "=r"(y) : "f"(x));
    return __uint_as_float(y);
}
// k-permutation within each 8-block: fragment pairs (tig, tig+4) become adjacent
__device__ __forceinline__ int p8(int i) {
    return (i & ~7) | (((i & 3) << 1) | ((i >> 2) & 1));
}

// ---------------- weight preprocess: transpose [K][N]->[N][K'], round tf32 ------
__global__ void wtrans_kernel(const float* __restrict__ src, float* __restrict__ dst,
                              int K, int N)
{
    __shared__ float tile[32][33];
    long zo = (long)blockIdx.z * K * N;
    int k0 = blockIdx.y * 32, n0 = blockIdx.x * 32;
    for (int i = threadIdx.y; i < 32; i += 8)
        tile[i][threadIdx.x] = src[zo + (long)(k0 + i)*N + n0 + threadIdx.x];
    __syncthreads();
    int k = k0 + threadIdx.x;
    int kp = p8(k);
    for (int i = threadIdx.y; i < 32; i += 8)
        dst[zo + (long)(n0 + i)*K + kp] = f2tf32(tile[threadIdx.x][i]);
}

// ---------------- LayerNorm: one block (256 thr) per row; writes permuted -------
__global__ void ln_kernel(const float* __restrict__ x, const float* __restrict__ g,
                          const float* __restrict__ b, float* __restrict__ out)
{
    __shared__ float red0[8], red1[8];
    __shared__ float mv0, mv1;
    int row = blockIdx.x;
    int t = threadIdx.x;
    float val = x[(long)row*DIM + t];
    float s1 = val, s2 = val*val;
    #pragma unroll
    for (int o = 16; o > 0; o >>= 1) {
        s1 += __shfl_xor_sync(0xffffffffu, s1, o);
        s2 += __shfl_xor_sync(0xffffffffu, s2, o);
    }
    if ((t & 31) == 0) { red0[t>>5] = s1; red1[t>>5] = s2; }
    __syncthreads();
    if (t == 0) {
        float a = 0.f, c = 0.f;
        #pragma unroll
        for (int i = 0; i < 8; i++) { a += red0[i]; c += red1[i]; }
        float m = a * (1.0f/DIM);
        mv0 = m;
        mv1 = rsqrtf(c * (1.0f/DIM) - m*m + 1e-5f);
    }
    __syncthreads();
    out[(long)row*DIM + p8(t)] = f2tf32((val - mv0) * mv1 * g[t] + b[t]);
}

// ---------------- MMA helpers ----------------
__device__ __forceinline__ void mma_tf32(float* d, float a0, float a1, float a2, float a3,
                                         float b0, float b1) {
    asm volatile(
        "mma.sync.aligned.m16n8k8.row.col.f32.tf32.tf32.f32 "
        "{%0,%1,%2,%3}, {%4,%5,%6,%7}, {%8,%9}, {%0,%1,%2,%3};"
        : "+f"(d[0]), "+f"(d[1]), "+f"(d[2]), "+f"(d[3])
        : "r"(__float_as_uint(a0)), "r"(__float_as_uint(a1)),
          "r"(__float_as_uint(a2)), "r"(__float_as_uint(a3)),
          "r"(__float_as_uint(b0)), "r"(__float_as_uint(b1)));
}

__device__ __forceinline__ void cpa16(unsigned d, const float* s) {
    asm volatile("cp.async.ca.shared.global [%0], [%1], 16;" :: "r"(d), "l"(s));
}

#define KS 24              // staging row stride (floats)
#define PSTRIDE 136        // P tile row stride (floats)

// ---------------- fused attention: S=QK^T, P=exp(S), O=P·V, O/=(rowsum*16) ------
// grid (SEQ/64, BH), 256 threads. q/k: [b,h,n,d'], v: [b,h,d,n'].
// dyn smem: SB[2][256*24] staging (S: Q rows 0-63 + K rows 64-191; PV: V rows 0-255),
//           Ps[64*136], rowsum[64].
__global__ __launch_bounds__(256)
void attn_kernel(const float* __restrict__ Qg, const float* __restrict__ Kg,
                 const float* __restrict__ Vg, float* __restrict__ Og)
{
    extern __shared__ float smem[];
    float* SB = smem;                       // 2 * 256*24
    float* Ps = smem + 2*256*KS;            // 64*136
    float* rowsum = Ps + 64*PSTRIDE;        // 64

    int z  = blockIdx.y;
    int q0 = blockIdx.x * 64;
    const float* qp = Qg + (long)z*SEQ*DIM;
    const float* kp = Kg + (long)z*SEQ*DIM;
    const float* vp = Vg + (long)z*DIM*SEQ;

    int t    = threadIdx.x;
    int lane = t & 31;
    int warp = t >> 5;
    int gid = lane >> 2;
    int tig = lane & 3;
    int wmS = (warp & 3) * 16, wnS = (warp >> 2) * 64;    // S: 64x128
    int wmV = (warp & 3) * 16, wnV = (warp >> 2) * 128;   // PV: 64x256

    if (t < 64) rowsum[t] = 0.f;

    unsigned sb = (unsigned)__cvta_generic_to_shared(SB);
    // S-phase staging addrs
    int lrow = t >> 1, lc = (t & 1) * 8;
    unsigned qd0 = sb + (unsigned)(lrow*KS + lc)*4u;            // rows 0-63 (t<128)
    unsigned kd0 = sb + (unsigned)((64 + lrow)*KS + lc)*4u;     // rows 64-191
    const float* qg0 = qp + (long)(q0 + lrow)*DIM + lc;
    // PV staging: row d = t, 16 floats/chunk
    unsigned vd0 = sb + (unsigned)(t*KS)*4u;

    float oacc[16][4];
    #pragma unroll
    for (int nt = 0; nt < 16; nt++)
        #pragma unroll
        for (int p = 0; p < 4; p++) oacc[nt][p] = 0.f;

    __syncthreads();   // rowsum init visible

    for (int kt = 0; kt < SEQ/128; kt++) {
        // ================= S phase: S[64][128] = Q·K^T over d=256 =================
        const float* kg0 = kp + (long)(kt*128 + lrow)*DIM + lc;
        float sacc[8][4];
        #pragma unroll
        for (int nt = 0; nt < 8; nt++)
            #pragma unroll
            for (int p = 0; p < 4; p++) sacc[nt][p] = 0.f;

        // prologue chunk 0 -> stage 0
        if (t < 128) { cpa16(qd0, qg0); cpa16(qd0 + 16, qg0 + 4); }
        cpa16(kd0, kg0); cpa16(kd0 + 16, kg0 + 4);
        asm volatile("cp.async.commit_group;");

        #pragma unroll 1
        for (int it = 0; it < 16; it++) {
            int s = it & 1;
            if (it + 1 < 16) {
                int k0 = (it + 1) * 16;
                unsigned off = (unsigned)((s^1)*256*KS)*4u;
                if (t < 128) { cpa16(qd0 + off, qg0 + k0); cpa16(qd0 + off + 16, qg0 + k0 + 4); }
                cpa16(kd0 + off, kg0 + k0); cpa16(kd0 + off + 16, kg0 + k0 + 4);
                asm volatile("cp.async.commit_group;");
                asm volatile("cp.async.wait_group 1;");
            } else {
                asm volatile("cp.async.wait_group 0;");
            }
            __syncthreads();

            const float* st = SB + s*256*KS;
            #pragma unroll
            for (int kk = 0; kk < 16; kk += 8) {
                float2 alo, ahi, bf[8];
                int r = wmS + gid;
                alo = *(const float2*)&st[r*KS + kk + 2*tig];
                ahi = *(const float2*)&st[(r+8)*KS + kk + 2*tig];
                #pragma unroll
                for (int nt = 0; nt < 8; nt++) {
                    int c = wnS + nt*8 + gid;
                    bf[nt] = *(const float2*)&st[(64 + c)*KS + kk + 2*tig];
                }
                #pragma unroll
                for (int nt = 0; nt < 8; nt++)
                    mma_tf32(sacc[nt], alo.x, ahi.x, alo.y, ahi.y, bf[nt].x, bf[nt].y);
            }
            __syncthreads();
        }

        // ================= P phase: exp, rowsum, store tf32 P =====================
        {
            float lsum0 = 0.f, lsum1 = 0.f;
            int r = wmS + gid;
            #pragma unroll
            for (int nt = 0; nt < 8; nt++) {
                int c = wnS + nt*8 + 2*tig;
                float e0 = expf(sacc[nt][0]);
                float e1 = expf(sacc[nt][1]);
                float e2 = expf(sacc[nt][2]);
                float e3 = expf(sacc[nt][3]);
                Ps[r*PSTRIDE + p8(c)]       = f2tf32(e0);
                Ps[r*PSTRIDE + p8(c+1)]     = f2tf32(e1);
                Ps[(r+8)*PSTRIDE + p8(c)]   = f2tf32(e2);
                Ps[(r+8)*PSTRIDE + p8(c+1)] = f2tf32(e3);
                lsum0 += e0 + e1;
                lsum1 += e2 + e3;
            }
            lsum0 += __shfl_xor_sync(0xffffffffu, lsum0, 1);
            lsum0 += __shfl_xor_sync(0xffffffffu, lsum0, 2);
            lsum1 += __shfl_xor_sync(0xffffffffu, lsum1, 1);
            lsum1 += __shfl_xor_sync(0xffffffffu, lsum1, 2);
            if (tig == 0) {
                atomicAdd(&rowsum[r], lsum0);
                atomicAdd(&rowsum[r+8], lsum1);
            }
        }
        __syncthreads();   // Ps complete before PV reads

        // ================= PV phase: O[64][256] += P·V^T over keys 128 ============
        const float* vg0 = vp + (long)t*SEQ + kt*128;
        cpa16(vd0, vg0); cpa16(vd0 + 16, vg0 + 4);
        cpa16(vd0 + 32, vg0 + 8); cpa16(vd0 + 48, vg0 + 12);
        asm volatile("cp.async.commit_group;");

        #pragma unroll 1
        for (int it = 0; it < 8; it++) {
            int s = it & 1;
            if (it + 1 < 8) {
                int k0 = (it + 1) * 16;
                unsigned off = (unsigned)((s^1)*256*KS)*4u;
                cpa16(vd0 + off, vg0 + k0); cpa16(vd0 + off + 16, vg0 + k0 + 4);
                cpa16(vd0 + off + 32, vg0 + k0 + 8); cpa16(vd0 + off + 48, vg0 + k0 + 12);
                asm volatile("cp.async.commit_group;");
                asm volatile("cp.async.wait_group 1;");
            } else {
                asm volatile("cp.async.wait_group 0;");
            }
            __syncthreads();

            const float* st = SB + s*256*KS;
            #pragma unroll
            for (int kk = 0; kk < 16; kk += 8) {
                float2 alo, ahi, bf[16];
                int r = wmV + gid;
                alo = *(const float2*)&Ps[r*PSTRIDE + it*16 + kk + 2*tig];
                ahi = *(const float2*)&Ps[(r+8)*PSTRIDE + it*16 + kk + 2*tig];
                #pragma unroll
                for (int nt = 0; nt < 16; nt++) {
                    int c = wnV + nt*8 + gid;
                    bf[nt] = *(const float2*)&st[c*KS + kk + 2*tig];
                }
                #pragma unroll
                for (int nt = 0; nt < 16; nt++)
                    mma_tf32(oacc[nt], alo.x, ahi.x, alo.y, ahi.y, bf[nt].x, bf[nt].y);
            }
            __syncthreads();
        }
        // trailing sync of PV loop also protects Ps overwrite next kt
    }

    // ================= epilogue: normalize, scatter to g_o ======================
    int b = z >> 3, hh = z & 7;
    #pragma unroll
    for (int nt = 0; nt < 16; nt++) {
        #pragma unroll
        for (int p = 0; p < 4; p++) {
            int r = wmV + gid + ((p >= 2) ? 8 : 0);
            int c = wnV + nt*8 + 2*tig + (p & 1);
            float inv = 1.0f / (rowsum[r] * 16.0f);
            Og[((long)(b*SEQ + q0 + r))*HID + hh*DIM + p8(c)] = f2tf32(oacc[nt][p] * inv);
        }
    }
}

// ---------------- tf32 TC GEMM: all operands [rows][k'] (TB form) ---------------
enum { EPI_QKV = 1, EPI_BIAS_RES = 2, EPI_BIAS_GELU = 3 };

#define TSZ (128*KS)       // one stage of one operand

template<int EPI>
__global__ __launch_bounds__(256, 2)
void gemm_tc(const float* __restrict__ A, const float* __restrict__ Bm,
             const float* __restrict__ bias, float* __restrict__ Cp,
             float* __restrict__ P1, float* __restrict__ P2,
             int Nc, int K, long sA, long sB, long sC)
{
    __shared__ float As[2][TSZ];
    __shared__ float Bs[2][TSZ];

    int z  = blockIdx.z;
    int m0 = blockIdx.y * 128;
    int n0 = blockIdx.x * 128;
    int t    = threadIdx.x;
    int lane = t & 31;
    int warp = t >> 5;
    int wm = (warp >> 1) * 32;
    int wn = (warp & 1) * 64;
    int gid = lane >> 2;
    int tig = lane & 3;

    int ar = t >> 1, ac = (t & 1) * 8;
    const float* apg = A + (long)z*sA + (long)(m0 + ar)*K + ac;
    const float* bpg = Bm + (long)z*sB + (long)(n0 + ar)*K + ac;
    unsigned asb = (unsigned)__cvta_generic_to_shared(&As[0][0]);
    unsigned bsb = (unsigned)__cvta_generic_to_shared(&Bs[0][0]);
    unsigned ad0 = asb + (unsigned)(ar*KS + ac)*4u;
    unsigned bd0 = bsb + (unsigned)(ar*KS + ac)*4u;

    float acc[2][8][4];
    #pragma unroll
    for (int mt = 0; mt < 2; mt++)
        #pragma unroll
        for (int nt = 0; nt < 8; nt++)
            #pragma unroll
            for (int p = 0; p < 4; p++) acc[mt][nt][p] = 0.f;

    cpa16(ad0, apg);  cpa16(ad0 + 16, apg + 4);
    cpa16(bd0, bpg);  cpa16(bd0 + 16, bpg + 4);
    asm volatile("cp.async.commit_group;");

    int niter = K / 16;
    for (int iter = 0; iter < niter; iter++) {
        int s = iter & 1;
        if (iter + 1 < niter) {
            int k0 = (iter + 1) * 16;
            unsigned ad = ad0 + (unsigned)((s^1)*TSZ)*4u;
            unsigned bd = bd0 + (unsigned)((s^1)*TSZ)*4u;
            cpa16(ad, apg + k0);  cpa16(ad + 16, apg + k0 + 4);
            cpa16(bd, bpg + k0);  cpa16(bd + 16, bpg + k0 + 4);
            asm volatile("cp.async.commit_group;");
            asm volatile("cp.async.wait_group 1;");
        } else {
            asm volatile("cp.async.wait_group 0;");
        }
        __syncthreads();

        const float* Asb = &As[s][0];
        const float* Bsb = &Bs[s][0];
        #pragma unroll
        for (int kk = 0; kk < 16; kk += 8) {
            float2 alo[2], ahi[2], bf[8];
            #pragma unroll
            for (int mt = 0; mt < 2; mt++) {
                int r = wm + mt*16 + gid;
                alo[mt] = *(const float2*)&Asb[r*KS + kk + 2*tig];
                ahi[mt] = *(const float2*)&Asb[(r+8)*KS + kk + 2*tig];
            }
            #pragma unroll
            for (int nt = 0; nt < 8; nt++) {
                int c = wn + nt*8 + gid;
                bf[nt] = *(const float2*)&Bsb[c*KS + kk + 2*tig];
            }
            #pragma unroll
            for (int mt = 0; mt < 2; mt++)
                #pragma unroll
                for (int nt = 0; nt < 8; nt++)
                    mma_tf32(acc[mt][nt], alo[mt].x, ahi[mt].x, alo[mt].y, ahi[mt].y,
                             bf[nt].x, bf[nt].y);
        }
        __syncthreads();
    }

    #pragma unroll
    for (int mt = 0; mt < 2; mt++) {
        #pragma unroll
        for (int nt = 0; nt < 8; nt++) {
            #pragma unroll
            for (int p = 0; p < 4; p++) {
                int row = m0 + wm + mt*16 + gid + ((p >= 2) ? 8 : 0);
                int col = n0 + wn + nt*8 + 2*tig + (p & 1);
                float v = acc[mt][nt][p];
                if (EPI == EPI_QKV) {
                    v += bias[col];
                    int si = col % 3;
                    int dc = (col / 3) & (DIM - 1);
                    int h  = col / (3*DIM);
                    int b  = row >> 10, n = row & (SEQ - 1);
                    if (si == 2) {             // v transposed: [b,h,d,n']
                        P2[(((long)(b*NH + h))*DIM + dc)*SEQ + p8(n)] = f2tf32(v);
                    } else {                   // q/k: [b,h,n,d']
                        float* dst = (si == 0) ? Cp : P1;
                        dst[(((long)(b*NH + h))*SEQ + n)*DIM + p8(dc)] = f2tf32(v);
                    }
                } else if (EPI == EPI_BIAS_RES) {
                    Cp[(long)row*Nc + col] += v + bias[col];
                } else {  // EPI_BIAS_GELU
                    float u = v + bias[col];
                    Cp[(long)row*Nc + p8(col)] = f2tf32(0.5f * u * (1.0f + erff(u * 0.70710678118654752f)));
                }
            }
        }
    }
}

// ---------------- host orchestration ----------------
extern "C" void kernel_launch(void* const* d_in, const int* in_sizes, int n_in,
                              void* d_out, int out_size)
{
    const float* x_in  = (const float*)d_in[0];
    const float* ln1_g = (const float*)d_in[1];
    const float* ln1_b = (const float*)d_in[2];
    const float* qkv_w = (const float*)d_in[3];
    const float* qkv_b = (const float*)d_in[4];
    const float* proj_w= (const float*)d_in[5];
    const float* proj_b= (const float*)d_in[6];
    const float* ln2_g = (const float*)d_in[7];
    const float* ln2_b = (const float*)d_in[8];
    const float* w1    = (const float*)d_in[9];
    const float* b1    = (const float*)d_in[10];
    const float* w2    = (const float*)d_in[11];
    const float* b2    = (const float*)d_in[12];
    float* out = (float*)d_out;

    float *h, *q, *k, *v, *o, *mh, *rqkvw, *rprojw, *rw1, *rw2;
    cudaGetSymbolAddress((void**)&h,  g_h);
    cudaGetSymbolAddress((void**)&q,  g_q);
    cudaGetSymbolAddress((void**)&k,  g_k);
    cudaGetSymbolAddress((void**)&v,  g_v);
    cudaGetSymbolAddress((void**)&o,  g_o);
    cudaGetSymbolAddress((void**)&mh, g_m);
    cudaGetSymbolAddress((void**)&rqkvw, g_qkvw);
    cudaGetSymbolAddress((void**)&rprojw, g_projw);
    cudaGetSymbolAddress((void**)&rw1, g_w1);
    cudaGetSymbolAddress((void**)&rw2, g_w2);

    const int ATTN_SMEM = (2*256*KS + 64*PSTRIDE + 64) * 4;   // ~84 KB
    cudaFuncSetAttribute(attn_kernel, cudaFuncAttributeMaxDynamicSharedMemorySize, ATTN_SMEM);

    // preprocess weights: transpose to [N][K'], round to tf32
    dim3 tb(32, 8);
    wtrans_kernel<<<dim3(3*HID/32, DIM/32, LNUM), tb>>>(qkv_w,  rqkvw,  DIM, 3*HID);
    wtrans_kernel<<<dim3(DIM/32, HID/32, LNUM), tb>>>(proj_w, rprojw, HID, DIM);
    wtrans_kernel<<<dim3(MLP/32, DIM/32, LNUM), tb>>>(w1, rw1, DIM, MLP);
    wtrans_kernel<<<dim3(DIM/32, MLP/32, LNUM), tb>>>(w2, rw2, MLP, DIM);

    cudaMemcpyAsync(out, x_in, sizeof(float)*(size_t)ROWS*DIM, cudaMemcpyDeviceToDevice);

    for (int i = 0; i < LNUM; i++) {
        // LN1 -> h (k')
        ln_kernel<<<ROWS, 256>>>(out, ln1_g + i*DIM, ln1_b + i*DIM, h);
        // QKV: h [8192][256'] x qkvwT [6144][256'] -> scatter q/k/v
        gemm_tc<EPI_QKV><<<dim3(3*HID/128, ROWS/128, 1), 256>>>(
            h, rqkvw + (long)i*DIM*3*HID, qkv_b + (long)i*3*HID,
            q, k, v, 3*HID, DIM, 0, 0, 0);
        // fused attention: scores never hit DRAM
        attn_kernel<<<dim3(SEQ/64, BH), 256, ATTN_SMEM>>>(q, k, v, o);
        // x += o @ proj_w + proj_b (o [m][2048'], projT [256][2048'])
        gemm_tc<EPI_BIAS_RES><<<dim3(DIM/128, ROWS/128, 1), 256>>>(
            o, rprojw + (long)i*HID*DIM, proj_b + (long)i*DIM,
            out, nullptr, nullptr, DIM, HID, 0, 0, 0);
        // LN2 -> h (k')
        ln_kernel<<<ROWS, 256>>>(out, ln2_g + i*DIM, ln2_b + i*DIM, h);
        // mh = gelu(h @ w1 + b1)  (w1T [1024][256'])
        gemm_tc<EPI_BIAS_GELU><<<dim3(MLP/128, ROWS/128, 1), 256>>>(
            h, rw1 + (long)i*DIM*MLP, b1 + (long)i*MLP,
            mh, nullptr, nullptr, MLP, DIM, 0, 0, 0);
        // x += mh @ w2 + b2  (mh [m][1024'], w2T [256][1024'])
        gemm_tc<EPI_BIAS_RES><<<dim3(DIM/128, ROWS/128, 1), 256>>>(
            mh, rw2 + (long)i*MLP*DIM, b2 + (long)i*DIM,
            out, nullptr, nullptr, DIM, MLP, 0, 0, 0);
    }
}

// round 7
// speedup vs baseline: 1.3208x; 1.3208x over previous
#include <cuda_runtime.h>
#include <math.h>

#define LNUM 4
#define DIM 256
#define NH 8
#define MLP 1024
#define BATCH 8
#define SEQ 1024
#define HID 2048            // NH * DIM
#define ROWS (BATCH*SEQ)    // 8192
#define BH (BATCH*NH)       // 64

// ---------------- scratch (device globals; no allocation allowed) ----------------
__device__ float g_h[ROWS*DIM];            // LN output (k-permuted)      8 MB
__device__ float g_q[BH*SEQ*DIM];          // q [b,h,n,d']                8 MB
__device__ float g_k[BH*SEQ*DIM];          // k [b,h,n,d']                8 MB
__device__ float g_v[BH*DIM*SEQ];          // v TRANSPOSED [b,h,d,n']     8 MB
__device__ float g_s[(size_t)BH*SEQ*SEQ];  // exp(scores) (cols perm)   256 MB
__device__ float g_rs[BH*SEQ];             // attention row sums         256 KB
__device__ float g_o[(size_t)ROWS*HID];    // attn out [b,n,(h d)']      64 MB
__device__ float g_m[ROWS*MLP];            // mlp hidden (permuted)      32 MB
// transposed + tf32-rounded + k-permuted weights
__device__ float g_qkvw[LNUM*DIM*3*HID];   // [l][6144][256']            25 MB
__device__ float g_projw[LNUM*HID*DIM];    // [l][256][2048']             8 MB
__device__ float g_w1[LNUM*DIM*MLP];       // [l][1024][256']             4 MB
__device__ float g_w2[LNUM*MLP*DIM];       // [l][256][1024']             4 MB

__device__ __forceinline__ float f2tf32(float x) {
    unsigned y;
    asm("cvt.rna.tf32.f32 %0, %1;" : "=r"(y) : "f"(x));
    return __uint_as_float(y);
}
// k-permutation within each 8-block: fragment pairs (tig, tig+4) become adjacent
__device__ __forceinline__ int p8(int i) {
    return (i & ~7) | (((i & 3) << 1) | ((i >> 2) & 1));
}

// ---------------- weight preprocess: transpose [K][N]->[N][K'], round tf32 ------
__global__ void wtrans_kernel(const float* __restrict__ src, float* __restrict__ dst,
                              int K, int N)
{
    __shared__ float tile[32][33];
    long zo = (long)blockIdx.z * K * N;
    int k0 = blockIdx.y * 32, n0 = blockIdx.x * 32;
    for (int i = threadIdx.y; i < 32; i += 8)
        tile[i][threadIdx.x] = src[zo + (long)(k0 + i)*N + n0 + threadIdx.x];
    __syncthreads();
    int k = k0 + threadIdx.x;
    int kp = p8(k);
    for (int i = threadIdx.y; i < 32; i += 8)
        dst[zo + (long)(n0 + i)*K + kp] = f2tf32(tile[threadIdx.x][i]);
}

// ---------------- LayerNorm: one block (256 thr) per row; writes permuted -------
__global__ void ln_kernel(const float* __restrict__ x, const float* __restrict__ g,
                          const float* __restrict__ b, float* __restrict__ out)
{
    __shared__ float red0[8], red1[8];
    __shared__ float mv0, mv1;
    int row = blockIdx.x;
    int t = threadIdx.x;
    float val = x[(long)row*DIM + t];
    float s1 = val, s2 = val*val;
    #pragma unroll
    for (int o = 16; o > 0; o >>= 1) {
        s1 += __shfl_xor_sync(0xffffffffu, s1, o);
        s2 += __shfl_xor_sync(0xffffffffu, s2, o);
    }
    if ((t & 31) == 0) { red0[t>>5] = s1; red1[t>>5] = s2; }
    __syncthreads();
    if (t == 0) {
        float a = 0.f, c = 0.f;
        #pragma unroll
        for (int i = 0; i < 8; i++) { a += red0[i]; c += red1[i]; }
        float m = a * (1.0f/DIM);
        mv0 = m;
        mv1 = rsqrtf(c * (1.0f/DIM) - m*m + 1e-5f);
    }
    __syncthreads();
    out[(long)row*DIM + p8(t)] = f2tf32((val - mv0) * mv1 * g[t] + b[t]);
}

// ---------------- tf32 TC GEMM: all operands [rows][k'] (TB form) ---------------
// C[m][n] = sum_k A[m][k'] B[n][k'].  Block 128x128, 256 thr, warp 32x64.
// cp.async double-buffered; fragment loads are conflict-free LDS.64.
// EPI_EXPSTORE: scores -> store tf32(exp(s)) permuted + rowsum atomics (P1 = rowsums)
// EPI_OSCAT:    PV     -> scale by 1/(rowsum*16) (P1 = rowsums), scatter to o
enum { EPI_EXPSTORE = 0, EPI_QKV = 1, EPI_BIAS_RES = 2, EPI_BIAS_GELU = 3, EPI_OSCAT = 4 };

__device__ __forceinline__ void mma_tf32(float* d, float a0, float a1, float a2, float a3,
                                         float b0, float b1) {
    asm volatile(
        "mma.sync.aligned.m16n8k8.row.col.f32.tf32.tf32.f32 "
        "{%0,%1,%2,%3}, {%4,%5,%6,%7}, {%8,%9}, {%0,%1,%2,%3};"
        : "+f"(d[0]), "+f"(d[1]), "+f"(d[2]), "+f"(d[3])
        : "r"(__float_as_uint(a0)), "r"(__float_as_uint(a1)),
          "r"(__float_as_uint(a2)), "r"(__float_as_uint(a3)),
          "r"(__float_as_uint(b0)), "r"(__float_as_uint(b1)));
}

__device__ __forceinline__ void cpa16(unsigned d, const float* s) {
    asm volatile("cp.async.ca.shared.global [%0], [%1], 16;" :: "r"(d), "l"(s));
}

#define KS 24              // smem row stride (floats): banks {0,8,16,24} per gid
#define TSZ (128*KS)       // one stage of one operand

template<int EPI>
__global__ __launch_bounds__(256, 2)
void gemm_tc(const float* __restrict__ A, const float* __restrict__ Bm,
             const float* __restrict__ bias, float* __restrict__ Cp,
             float* __restrict__ P1, float* __restrict__ P2,
             int Nc, int K, long sA, long sB, long sC)
{
    __shared__ float As[2][TSZ];
    __shared__ float Bs[2][TSZ];

    int z  = blockIdx.z;
    int m0 = blockIdx.y * 128;
    int n0 = blockIdx.x * 128;
    int t    = threadIdx.x;
    int lane = t & 31;
    int warp = t >> 5;
    int wm = (warp >> 1) * 32;
    int wn = (warp & 1) * 64;
    int gid = lane >> 2;
    int tig = lane & 3;

    int ar = t >> 1, ac = (t & 1) * 8;
    const float* apg = A + (long)z*sA + (long)(m0 + ar)*K + ac;
    const float* bpg = Bm + (long)z*sB + (long)(n0 + ar)*K + ac;
    unsigned asb = (unsigned)__cvta_generic_to_shared(&As[0][0]);
    unsigned bsb = (unsigned)__cvta_generic_to_shared(&Bs[0][0]);
    unsigned ad0 = asb + (unsigned)(ar*KS + ac)*4u;
    unsigned bd0 = bsb + (unsigned)(ar*KS + ac)*4u;

    float acc[2][8][4];
    #pragma unroll
    for (int mt = 0; mt < 2; mt++)
        #pragma unroll
        for (int nt = 0; nt < 8; nt++)
            #pragma unroll
            for (int p = 0; p < 4; p++) acc[mt][nt][p] = 0.f;

    // prologue: stage 0
    cpa16(ad0, apg);  cpa16(ad0 + 16, apg + 4);
    cpa16(bd0, bpg);  cpa16(bd0 + 16, bpg + 4);
    asm volatile("cp.async.commit_group;");

    int niter = K / 16;
    for (int iter = 0; iter < niter; iter++) {
        int s = iter & 1;
        if (iter + 1 < niter) {
            int k0 = (iter + 1) * 16;
            unsigned ad = ad0 + (unsigned)((s^1)*TSZ)*4u;
            unsigned bd = bd0 + (unsigned)((s^1)*TSZ)*4u;
            cpa16(ad, apg + k0);  cpa16(ad + 16, apg + k0 + 4);
            cpa16(bd, bpg + k0);  cpa16(bd + 16, bpg + k0 + 4);
            asm volatile("cp.async.commit_group;");
            asm volatile("cp.async.wait_group 1;");
        } else {
            asm volatile("cp.async.wait_group 0;");
        }
        __syncthreads();

        const float* Asb = &As[s][0];
        const float* Bsb = &Bs[s][0];
        #pragma unroll
        for (int kk = 0; kk < 16; kk += 8) {
            float2 alo[2], ahi[2], bf[8];
            #pragma unroll
            for (int mt = 0; mt < 2; mt++) {
                int r = wm + mt*16 + gid;
                alo[mt] = *(const float2*)&Asb[r*KS + kk + 2*tig];
                ahi[mt] = *(const float2*)&Asb[(r+8)*KS + kk + 2*tig];
            }
            #pragma unroll
            for (int nt = 0; nt < 8; nt++) {
                int c = wn + nt*8 + gid;
                bf[nt] = *(const float2*)&Bsb[c*KS + kk + 2*tig];
            }
            #pragma unroll
            for (int mt = 0; mt < 2; mt++)
                #pragma unroll
                for (int nt = 0; nt < 8; nt++)
                    mma_tf32(acc[mt][nt], alo[mt].x, ahi[mt].x, alo[mt].y, ahi[mt].y,
                             bf[nt].x, bf[nt].y);
        }
        __syncthreads();
    }

    // ---------------- epilogue ----------------
    if (EPI == EPI_EXPSTORE) {
        // scores: e = exp(s); store tf32 e (cols permuted); accumulate row sums
        float ls[2][2] = {{0.f, 0.f}, {0.f, 0.f}};
        #pragma unroll
        for (int mt = 0; mt < 2; mt++) {
            #pragma unroll
            for (int nt = 0; nt < 8; nt++) {
                #pragma unroll
                for (int p = 0; p < 4; p++) {
                    int hlf = (p >= 2) ? 1 : 0;
                    int row = m0 + wm + mt*16 + gid + hlf*8;
                    int col = n0 + wn + nt*8 + 2*tig + (p & 1);
                    float e = expf(acc[mt][nt][p]);
                    Cp[(long)z*sC + (long)row*Nc + p8(col)] = f2tf32(e);
                    ls[mt][hlf] += e;
                }
            }
        }
        // reduce across the 4-thread group (same rows), then one atomic per row
        #pragma unroll
        for (int mt = 0; mt < 2; mt++)
            #pragma unroll
            for (int hlf = 0; hlf < 2; hlf++) {
                float v = ls[mt][hlf];
                v += __shfl_xor_sync(0xffffffffu, v, 1);
                v += __shfl_xor_sync(0xffffffffu, v, 2);
                if (tig == 0) {
                    int row = m0 + wm + mt*16 + gid + hlf*8;
                    atomicAdd(&P1[(long)z*SEQ + row], v);
                }
            }
        return;
    }

    #pragma unroll
    for (int mt = 0; mt < 2; mt++) {
        #pragma unroll
        for (int nt = 0; nt < 8; nt++) {
            #pragma unroll
            for (int p = 0; p < 4; p++) {
                int row = m0 + wm + mt*16 + gid + ((p >= 2) ? 8 : 0);
                int col = n0 + wn + nt*8 + 2*tig + (p & 1);
                float v = acc[mt][nt][p];
                if (EPI == EPI_QKV) {
                    v += bias[col];
                    int si = col % 3;
                    int dc = (col / 3) & (DIM - 1);
                    int h  = col / (3*DIM);
                    int b  = row >> 10, n = row & (SEQ - 1);
                    if (si == 2) {             // v transposed: [b,h,d,n']
                        P2[(((long)(b*NH + h))*DIM + dc)*SEQ + p8(n)] = f2tf32(v);
                    } else {                   // q/k: [b,h,n,d']
                        float* dst = (si == 0) ? Cp : P1;
                        dst[(((long)(b*NH + h))*SEQ + n)*DIM + p8(dc)] = f2tf32(v);
                    }
                } else if (EPI == EPI_BIAS_RES) {   // residual: logical layout
                    Cp[(long)row*Nc + col] += v + bias[col];
                } else if (EPI == EPI_BIAS_GELU) {  // mlp hidden: permuted
                    float u = v + bias[col];
                    Cp[(long)row*Nc + p8(col)] = f2tf32(0.5f * u * (1.0f + erff(u * 0.70710678118654752f)));
                } else {                            // EPI_OSCAT: normalize + scatter
                    int b = z >> 3, h = z & 7;
                    float inv = 1.0f / (P1[(long)z*SEQ + row] * 16.0f);
                    Cp[((long)(b*SEQ + row))*HID + h*DIM + p8(col)] = f2tf32(v * inv);
                }
            }
        }
    }
}

// ---------------- host orchestration ----------------
extern "C" void kernel_launch(void* const* d_in, const int* in_sizes, int n_in,
                              void* d_out, int out_size)
{
    const float* x_in  = (const float*)d_in[0];
    const float* ln1_g = (const float*)d_in[1];
    const float* ln1_b = (const float*)d_in[2];
    const float* qkv_w = (const float*)d_in[3];
    const float* qkv_b = (const float*)d_in[4];
    const float* proj_w= (const float*)d_in[5];
    const float* proj_b= (const float*)d_in[6];
    const float* ln2_g = (const float*)d_in[7];
    const float* ln2_b = (const float*)d_in[8];
    const float* w1    = (const float*)d_in[9];
    const float* b1    = (const float*)d_in[10];
    const float* w2    = (const float*)d_in[11];
    const float* b2    = (const float*)d_in[12];
    float* out = (float*)d_out;

    float *h, *q, *k, *v, *s, *rs, *o, *mh, *rqkvw, *rprojw, *rw1, *rw2;
    cudaGetSymbolAddress((void**)&h,  g_h);
    cudaGetSymbolAddress((void**)&q,  g_q);
    cudaGetSymbolAddress((void**)&k,  g_k);
    cudaGetSymbolAddress((void**)&v,  g_v);
    cudaGetSymbolAddress((void**)&s,  g_s);
    cudaGetSymbolAddress((void**)&rs, g_rs);
    cudaGetSymbolAddress((void**)&o,  g_o);
    cudaGetSymbolAddress((void**)&mh, g_m);
    cudaGetSymbolAddress((void**)&rqkvw, g_qkvw);
    cudaGetSymbolAddress((void**)&rprojw, g_projw);
    cudaGetSymbolAddress((void**)&rw1, g_w1);
    cudaGetSymbolAddress((void**)&rw2, g_w2);

    // preprocess weights: transpose to [N][K'], round to tf32
    dim3 tb(32, 8);
    wtrans_kernel<<<dim3(3*HID/32, DIM/32, LNUM), tb>>>(qkv_w,  rqkvw,  DIM, 3*HID);
    wtrans_kernel<<<dim3(DIM/32, HID/32, LNUM), tb>>>(proj_w, rprojw, HID, DIM);
    wtrans_kernel<<<dim3(MLP/32, DIM/32, LNUM), tb>>>(w1, rw1, DIM, MLP);
    wtrans_kernel<<<dim3(DIM/32, MLP/32, LNUM), tb>>>(w2, rw2, MLP, DIM);

    cudaMemcpyAsync(out, x_in, sizeof(float)*(size_t)ROWS*DIM, cudaMemcpyDeviceToDevice);

    for (int i = 0; i < LNUM; i++) {
        // LN1 -> h (k')
        ln_kernel<<<ROWS, 256>>>(out, ln1_g + i*DIM, ln1_b + i*DIM, h);
        // QKV: h [8192][256'] x qkvwT [6144][256'] -> scatter q/k/v
        gemm_tc<EPI_QKV><<<dim3(3*HID/128, ROWS/128, 1), 256>>>(
            h, rqkvw + (long)i*DIM*3*HID, qkv_b + (long)i*3*HID,
            q, k, v, 3*HID, DIM, 0, 0, 0);
        // zero rowsums, then scores = exp(q @ k^T) with fused rowsum
        cudaMemsetAsync(rs, 0, sizeof(float)*BH*SEQ);
        gemm_tc<EPI_EXPSTORE><<<dim3(SEQ/128, SEQ/128, BH), 256>>>(
            q, k, nullptr, s, rs, nullptr,
            SEQ, DIM, (long)SEQ*DIM, (long)SEQ*DIM, (long)SEQ*SEQ);
        // o = P @ V with fused 1/(rowsum*16); scatter o [b,n,(h d)']
        gemm_tc<EPI_OSCAT><<<dim3(DIM/128, SEQ/128, BH), 256>>>(
            s, v, nullptr, o, rs, nullptr,
            DIM, SEQ, (long)SEQ*SEQ, (long)DIM*SEQ, 0);
        // x += o @ proj_w + proj_b (o [m][2048'], projT [256][2048'])
        gemm_tc<EPI_BIAS_RES><<<dim3(DIM/128, ROWS/128, 1), 256>>>(
            o, rprojw + (long)i*HID*DIM, proj_b + (long)i*DIM,
            out, nullptr, nullptr, DIM, HID, 0, 0, 0);
        // LN2 -> h (k')
        ln_kernel<<<ROWS, 256>>>(out, ln2_g + i*DIM, ln2_b + i*DIM, h);
        // mh = gelu(h @ w1 + b1)  (w1T [1024][256'])
        gemm_tc<EPI_BIAS_GELU><<<dim3(MLP/128, ROWS/128, 1), 256>>>(
            h, rw1 + (long)i*DIM*MLP, b1 + (long)i*MLP,
            mh, nullptr, nullptr, MLP, DIM, 0, 0, 0);
        // x += mh @ w2 + b2  (mh [m][1024'], w2T [256][1024'])
        gemm_tc<EPI_BIAS_RES><<<dim3(DIM/128, ROWS/128, 1), 256>>>(
            mh, rw2 + (long)i*MLP*DIM, b2 + (long)i*DIM,
            out, nullptr, nullptr, DIM, MLP, 0, 0, 0);
    }
}

// round 8
// speedup vs baseline: 1.7043x; 1.2903x over previous
#include <cuda_runtime.h>
#include <cuda_bf16.h>
#include <math.h>

#define LNUM 4
#define DIM 256
#define NH 8
#define MLP 1024
#define BATCH 8
#define SEQ 1024
#define HID 2048            // NH * DIM
#define ROWS (BATCH*SEQ)    // 8192
#define BH (BATCH*NH)       // 64

// ---------------- scratch (device globals; no allocation allowed) ----------------
__device__ float g_h[ROWS*DIM];            // LN output (k-permuted, tf32)
__device__ float g_q[BH*SEQ*DIM/2];        // q bf16 [b,h,n,d]
__device__ float g_k[BH*SEQ*DIM/2];        // k bf16 [b,h,n,d]
__device__ float g_v[BH*DIM*SEQ/2];        // v bf16 TRANSPOSED [b,h,d,n]
__device__ float g_s[(size_t)BH*SEQ*SEQ/2];// exp(scores) bf16 [bh][q][k]
__device__ float g_rs[BH*SEQ];             // attention row sums
__device__ float g_o[(size_t)ROWS*HID];    // attn out [b,n,(h d)'] tf32
__device__ float g_m[ROWS*MLP];            // mlp hidden (permuted, tf32)
// transposed + tf32-rounded + k-permuted weights
__device__ float g_qkvw[LNUM*DIM*3*HID];
__device__ float g_projw[LNUM*HID*DIM];
__device__ float g_w1[LNUM*DIM*MLP];
__device__ float g_w2[LNUM*MLP*DIM];

__device__ __forceinline__ float f2tf32(float x) {
    unsigned y;
    asm("cvt.rna.tf32.f32 %0, %1;" : "=r"(y) : "f"(x));
    return __uint_as_float(y);
}
// k-permutation within each 8-block (tf32 path only)
__device__ __forceinline__ int p8(int i) {
    return (i & ~7) | (((i & 3) << 1) | ((i >> 2) & 1));
}

// ---------------- weight preprocess: transpose [K][N]->[N][K'], round tf32 ------
__global__ void wtrans_kernel(const float* __restrict__ src, float* __restrict__ dst,
                              int K, int N)
{
    __shared__ float tile[32][33];
    long zo = (long)blockIdx.z * K * N;
    int k0 = blockIdx.y * 32, n0 = blockIdx.x * 32;
    for (int i = threadIdx.y; i < 32; i += 8)
        tile[i][threadIdx.x] = src[zo + (long)(k0 + i)*N + n0 + threadIdx.x];
    __syncthreads();
    int k = k0 + threadIdx.x;
    int kp = p8(k);
    for (int i = threadIdx.y; i < 32; i += 8)
        dst[zo + (long)(n0 + i)*K + kp] = f2tf32(tile[threadIdx.x][i]);
}

// ---------------- LayerNorm: one block (256 thr) per row; writes permuted -------
__global__ void ln_kernel(const float* __restrict__ x, const float* __restrict__ g,
                          const float* __restrict__ b, float* __restrict__ out)
{
    __shared__ float red0[8], red1[8];
    __shared__ float mv0, mv1;
    int row = blockIdx.x;
    int t = threadIdx.x;
    float val = x[(long)row*DIM + t];
    float s1 = val, s2 = val*val;
    #pragma unroll
    for (int o = 16; o > 0; o >>= 1) {
        s1 += __shfl_xor_sync(0xffffffffu, s1, o);
        s2 += __shfl_xor_sync(0xffffffffu, s2, o);
    }
    if ((t & 31) == 0) { red0[t>>5] = s1; red1[t>>5] = s2; }
    __syncthreads();
    if (t == 0) {
        float a = 0.f, c = 0.f;
        #pragma unroll
        for (int i = 0; i < 8; i++) { a += red0[i]; c += red1[i]; }
        float m = a * (1.0f/DIM);
        mv0 = m;
        mv1 = rsqrtf(c * (1.0f/DIM) - m*m + 1e-5f);
    }
    __syncthreads();
    out[(long)row*DIM + p8(t)] = f2tf32((val - mv0) * mv1 * g[t] + b[t]);
}

// ---------------- common helpers ----------------
__device__ __forceinline__ void mma_tf32(float* d, float a0, float a1, float a2, float a3,
                                         float b0, float b1) {
    asm volatile(
        "mma.sync.aligned.m16n8k8.row.col.f32.tf32.tf32.f32 "
        "{%0,%1,%2,%3}, {%4,%5,%6,%7}, {%8,%9}, {%0,%1,%2,%3};"
        : "+f"(d[0]), "+f"(d[1]), "+f"(d[2]), "+f"(d[3])
        : "r"(__float_as_uint(a0)), "r"(__float_as_uint(a1)),
          "r"(__float_as_uint(a2)), "r"(__float_as_uint(a3)),
          "r"(__float_as_uint(b0)), "r"(__float_as_uint(b1)));
}
__device__ __forceinline__ void mma_bf16(float* d, unsigned a0, unsigned a1, unsigned a2,
                                         unsigned a3, unsigned b0, unsigned b1) {
    asm volatile(
        "mma.sync.aligned.m16n8k16.row.col.f32.bf16.bf16.f32 "
        "{%0,%1,%2,%3}, {%4,%5,%6,%7}, {%8,%9}, {%0,%1,%2,%3};"
        : "+f"(d[0]), "+f"(d[1]), "+f"(d[2]), "+f"(d[3])
        : "r"(a0), "r"(a1), "r"(a2), "r"(a3), "r"(b0), "r"(b1));
}
__device__ __forceinline__ void cpa16(unsigned d, const void* s) {
    asm volatile("cp.async.ca.shared.global [%0], [%1], 16;" :: "r"(d), "l"(s));
}

// ================================================================================
// tf32 TC GEMM (dense path): operands [rows][k'] tf32-rounded fp32.
// supports split-K via blockIdx.z chunk (sA/sB = chunk k-offset), ldk = row stride.
// ================================================================================
enum { EPI_QKV = 1, EPI_BIAS_RES = 2, EPI_BIAS_GELU = 3 };

#define KS 24
#define TSZ (128*KS)

template<int EPI>
__global__ __launch_bounds__(256, 2)
void gemm_tc(const float* __restrict__ A, const float* __restrict__ Bm,
             const float* __restrict__ bias, float* __restrict__ Cp,
             float* __restrict__ P1, float* __restrict__ P2,
             int Nc, int K, int ldk, long sA, long sB)
{
    __shared__ float As[2][TSZ];
    __shared__ float Bs[2][TSZ];

    int z  = blockIdx.z;
    int m0 = blockIdx.y * 128;
    int n0 = blockIdx.x * 128;
    int t    = threadIdx.x;
    int lane = t & 31;
    int warp = t >> 5;
    int wm = (warp >> 1) * 32;
    int wn = (warp & 1) * 64;
    int gid = lane >> 2;
    int tig = lane & 3;

    int ar = t >> 1, ac = (t & 1) * 8;
    const float* apg = A + (long)z*sA + (long)(m0 + ar)*ldk + ac;
    const float* bpg = Bm + (long)z*sB + (long)(n0 + ar)*ldk + ac;
    unsigned asb = (unsigned)__cvta_generic_to_shared(&As[0][0]);
    unsigned bsb = (unsigned)__cvta_generic_to_shared(&Bs[0][0]);
    unsigned ad0 = asb + (unsigned)(ar*KS + ac)*4u;
    unsigned bd0 = bsb + (unsigned)(ar*KS + ac)*4u;

    float acc[2][8][4];
    #pragma unroll
    for (int mt = 0; mt < 2; mt++)
        #pragma unroll
        for (int nt = 0; nt < 8; nt++)
            #pragma unroll
            for (int p = 0; p < 4; p++) acc[mt][nt][p] = 0.f;

    cpa16(ad0, apg);  cpa16(ad0 + 16, apg + 4);
    cpa16(bd0, bpg);  cpa16(bd0 + 16, bpg + 4);
    asm volatile("cp.async.commit_group;");

    int niter = K / 16;
    for (int iter = 0; iter < niter; iter++) {
        int s = iter & 1;
        if (iter + 1 < niter) {
            int k0 = (iter + 1) * 16;
            unsigned ad = ad0 + (unsigned)((s^1)*TSZ)*4u;
            unsigned bd = bd0 + (unsigned)((s^1)*TSZ)*4u;
            cpa16(ad, apg + k0);  cpa16(ad + 16, apg + k0 + 4);
            cpa16(bd, bpg + k0);  cpa16(bd + 16, bpg + k0 + 4);
            asm volatile("cp.async.commit_group;");
            asm volatile("cp.async.wait_group 1;");
        } else {
            asm volatile("cp.async.wait_group 0;");
        }
        __syncthreads();

        const float* Asb = &As[s][0];
        const float* Bsb = &Bs[s][0];
        #pragma unroll
        for (int kk = 0; kk < 16; kk += 8) {
            float2 alo[2], ahi[2], bf[8];
            #pragma unroll
            for (int mt = 0; mt < 2; mt++) {
                int r = wm + mt*16 + gid;
                alo[mt] = *(const float2*)&Asb[r*KS + kk + 2*tig];
                ahi[mt] = *(const float2*)&Asb[(r+8)*KS + kk + 2*tig];
            }
            #pragma unroll
            for (int nt = 0; nt < 8; nt++) {
                int c = wn + nt*8 + gid;
                bf[nt] = *(const float2*)&Bsb[c*KS + kk + 2*tig];
            }
            #pragma unroll
            for (int mt = 0; mt < 2; mt++)
                #pragma unroll
                for (int nt = 0; nt < 8; nt++)
                    mma_tf32(acc[mt][nt], alo[mt].x, ahi[mt].x, alo[mt].y, ahi[mt].y,
                             bf[nt].x, bf[nt].y);
        }
        __syncthreads();
    }

    #pragma unroll
    for (int mt = 0; mt < 2; mt++) {
        #pragma unroll
        for (int nt = 0; nt < 8; nt++) {
            #pragma unroll
            for (int p = 0; p < 4; p++) {
                int row = m0 + wm + mt*16 + gid + ((p >= 2) ? 8 : 0);
                int col = n0 + wn + nt*8 + 2*tig + (p & 1);
                float v = acc[mt][nt][p];
                if (EPI == EPI_QKV) {
                    v += bias[col];
                    int si = col % 3;
                    int dc = (col / 3) & (DIM - 1);
                    int h  = col / (3*DIM);
                    int b  = row >> 10, n = row & (SEQ - 1);
                    long bh = b*NH + h;
                    if (si == 2) {       // v bf16 transposed [b,h,d,n]
                        ((__nv_bfloat16*)P2)[(bh*DIM + dc)*SEQ + n] = __float2bfloat16(v);
                    } else {             // q/k bf16 [b,h,n,d]
                        __nv_bfloat16* dst = (__nv_bfloat16*)((si == 0) ? Cp : P1);
                        dst[(bh*SEQ + n)*DIM + dc] = __float2bfloat16(v);
                    }
                } else if (EPI == EPI_BIAS_RES) {   // split-K residual: atomic
                    float add = v + ((z == 0) ? bias[col] : 0.f);
                    atomicAdd(&Cp[(long)row*Nc + col], add);
                } else {                            // EPI_BIAS_GELU (permuted out)
                    float u = v + bias[col];
                    Cp[(long)row*Nc + p8(col)] = f2tf32(0.5f * u * (1.0f + erff(u * 0.70710678118654752f)));
                }
            }
        }
    }
}

// ================================================================================
// bf16 TC GEMM (attention path): operands [rows][k] bf16, m16n8k16.
// EPI_EXPSTORE: out = bf16 exp(acc), rowsum atomics.  EPI_OSCAT: normalize+scatter.
// ================================================================================
enum { EPIB_EXPSTORE = 0, EPIB_OSCAT = 1 };

#define BKS 80             // bytes per staged row (64B data + 16B pad): conflict-free
#define BTSZ (128*BKS)

template<int EPI>
__global__ __launch_bounds__(256, 2)
void gemm_bf(const __nv_bfloat16* __restrict__ A, const __nv_bfloat16* __restrict__ Bm,
             void* __restrict__ Cp, float* __restrict__ RS,
             int Nc, int K, long sA, long sB, long sC)
{
    __shared__ char As[2][BTSZ];
    __shared__ char Bs[2][BTSZ];

    int z  = blockIdx.z;
    int m0 = blockIdx.y * 128;
    int n0 = blockIdx.x * 128;
    int t    = threadIdx.x;
    int lane = t & 31;
    int warp = t >> 5;
    int wm = (warp >> 1) * 32;
    int wn = (warp & 1) * 64;
    int gid = lane >> 2;
    int tig = lane & 3;

    // loader: 128 rows x 64B per operand per iter; 2 threads/row, 32B each
    int lr = t >> 1, lc = (t & 1) * 16;     // lc in bf16 elems
    const __nv_bfloat16* apg = A + z*sA + (long)(m0 + lr)*K + lc;
    const __nv_bfloat16* bpg = Bm + z*sB + (long)(n0 + lr)*K + lc;
    unsigned asb = (unsigned)__cvta_generic_to_shared(&As[0][0]);
    unsigned bsb = (unsigned)__cvta_generic_to_shared(&Bs[0][0]);
    unsigned ad0 = asb + (unsigned)(lr*BKS + (t & 1)*32);
    unsigned bd0 = bsb + (unsigned)(lr*BKS + (t & 1)*32);

    float acc[2][8][4];
    #pragma unroll
    for (int mt = 0; mt < 2; mt++)
        #pragma unroll
        for (int nt = 0; nt < 8; nt++)
            #pragma unroll
            for (int p = 0; p < 4; p++) acc[mt][nt][p] = 0.f;

    cpa16(ad0, apg);  cpa16(ad0 + 16, apg + 8);
    cpa16(bd0, bpg);  cpa16(bd0 + 16, bpg + 8);
    asm volatile("cp.async.commit_group;");

    int niter = K / 32;
    for (int iter = 0; iter < niter; iter++) {
        int s = iter & 1;
        if (iter + 1 < niter) {
            int k0 = (iter + 1) * 32;
            unsigned ad = ad0 + (unsigned)((s^1)*BTSZ);
            unsigned bd = bd0 + (unsigned)((s^1)*BTSZ);
            cpa16(ad, apg + k0);  cpa16(ad + 16, apg + k0 + 8);
            cpa16(bd, bpg + k0);  cpa16(bd + 16, bpg + k0 + 8);
            asm volatile("cp.async.commit_group;");
            asm volatile("cp.async.wait_group 1;");
        } else {
            asm volatile("cp.async.wait_group 0;");
        }
        __syncthreads();

        const char* Ab_ = &As[s][0];
        const char* Bb_ = &Bs[s][0];
        #pragma unroll
        for (int kkb = 0; kkb < 64; kkb += 32) {   // two k16 halves (32B each)
            unsigned af[2][4], bf[8][2];
            #pragma unroll
            for (int mt = 0; mt < 2; mt++) {
                int r = wm + mt*16 + gid;
                const char* pa = Ab_ + r*BKS + kkb + 4*tig;
                const char* pa8 = Ab_ + (r+8)*BKS + kkb + 4*tig;
                af[mt][0] = *(const unsigned*)pa;
                af[mt][1] = *(const unsigned*)pa8;
                af[mt][2] = *(const unsigned*)(pa + 16);
                af[mt][3] = *(const unsigned*)(pa8 + 16);
            }
            #pragma unroll
            for (int nt = 0; nt < 8; nt++) {
                int c = wn + nt*8 + gid;
                const char* pb = Bb_ + c*BKS + kkb + 4*tig;
                bf[nt][0] = *(const unsigned*)pb;
                bf[nt][1] = *(const unsigned*)(pb + 16);
            }
            #pragma unroll
            for (int mt = 0; mt < 2; mt++)
                #pragma unroll
                for (int nt = 0; nt < 8; nt++)
                    mma_bf16(acc[mt][nt], af[mt][0], af[mt][1], af[mt][2], af[mt][3],
                             bf[nt][0], bf[nt][1]);
        }
        __syncthreads();
    }

    if (EPI == EPIB_EXPSTORE) {
        __nv_bfloat16* Pb = (__nv_bfloat16*)Cp;
        float ls[2][2] = {{0.f, 0.f}, {0.f, 0.f}};
        #pragma unroll
        for (int mt = 0; mt < 2; mt++) {
            int r = m0 + wm + mt*16 + gid;
            #pragma unroll
            for (int nt = 0; nt < 8; nt++) {
                int c = n0 + wn + nt*8 + 2*tig;
                float e0 = expf(acc[mt][nt][0]);
                float e1 = expf(acc[mt][nt][1]);
                float e2 = expf(acc[mt][nt][2]);
                float e3 = expf(acc[mt][nt][3]);
                __nv_bfloat162 lo, hi;
                lo.x = __float2bfloat16(e0); lo.y = __float2bfloat16(e1);
                hi.x = __float2bfloat16(e2); hi.y = __float2bfloat16(e3);
                *(__nv_bfloat162*)&Pb[(long)z*sC + (long)r*Nc + c]     = lo;
                *(__nv_bfloat162*)&Pb[(long)z*sC + (long)(r+8)*Nc + c] = hi;
                ls[mt][0] += e0 + e1;
                ls[mt][1] += e2 + e3;
            }
        }
        #pragma unroll
        for (int mt = 0; mt < 2; mt++)
            #pragma unroll
            for (int hlf = 0; hlf < 2; hlf++) {
                float v = ls[mt][hlf];
                v += __shfl_xor_sync(0xffffffffu, v, 1);
                v += __shfl_xor_sync(0xffffffffu, v, 2);
                if (tig == 0) {
                    int row = m0 + wm + mt*16 + gid + hlf*8;
                    atomicAdd(&RS[(long)z*SEQ + row], v);
                }
            }
    } else {   // EPIB_OSCAT: o tf32 (permuted), normalized
        float* Of = (float*)Cp;
        int b = z >> 3, h = z & 7;
        #pragma unroll
        for (int mt = 0; mt < 2; mt++) {
            #pragma unroll
            for (int p = 0; p < 4; p++) {
                int row = m0 + wm + mt*16 + gid + ((p >= 2) ? 8 : 0);
                float inv = 1.0f / (RS[(long)z*SEQ + row] * 16.0f);
                #pragma unroll
                for (int nt = 0; nt < 8; nt++) {
                    int col = n0 + wn + nt*8 + 2*tig + (p & 1);
                    Of[((long)(b*SEQ + row))*HID + h*DIM + p8(col)] =
                        f2tf32(acc[mt][nt][p] * inv);
                }
            }
        }
    }
}

// ---------------- host orchestration ----------------
extern "C" void kernel_launch(void* const* d_in, const int* in_sizes, int n_in,
                              void* d_out, int out_size)
{
    const float* x_in  = (const float*)d_in[0];
    const float* ln1_g = (const float*)d_in[1];
    const float* ln1_b = (const float*)d_in[2];
    const float* qkv_w = (const float*)d_in[3];
    const float* qkv_b = (const float*)d_in[4];
    const float* proj_w= (const float*)d_in[5];
    const float* proj_b= (const float*)d_in[6];
    const float* ln2_g = (const float*)d_in[7];
    const float* ln2_b = (const float*)d_in[8];
    const float* w1    = (const float*)d_in[9];
    const float* b1    = (const float*)d_in[10];
    const float* w2    = (const float*)d_in[11];
    const float* b2    = (const float*)d_in[12];
    float* out = (float*)d_out;

    float *h, *q, *k, *v, *s, *rs, *o, *mh, *rqkvw, *rprojw, *rw1, *rw2;
    cudaGetSymbolAddress((void**)&h,  g_h);
    cudaGetSymbolAddress((void**)&q,  g_q);
    cudaGetSymbolAddress((void**)&k,  g_k);
    cudaGetSymbolAddress((void**)&v,  g_v);
    cudaGetSymbolAddress((void**)&s,  g_s);
    cudaGetSymbolAddress((void**)&rs, g_rs);
    cudaGetSymbolAddress((void**)&o,  g_o);
    cudaGetSymbolAddress((void**)&mh, g_m);
    cudaGetSymbolAddress((void**)&rqkvw, g_qkvw);
    cudaGetSymbolAddress((void**)&rprojw, g_projw);
    cudaGetSymbolAddress((void**)&rw1, g_w1);
    cudaGetSymbolAddress((void**)&rw2, g_w2);

    // preprocess weights: transpose to [N][K'], round to tf32
    dim3 tb(32, 8);
    wtrans_kernel<<<dim3(3*HID/32, DIM/32, LNUM), tb>>>(qkv_w,  rqkvw,  DIM, 3*HID);
    wtrans_kernel<<<dim3(DIM/32, HID/32, LNUM), tb>>>(proj_w, rprojw, HID, DIM);
    wtrans_kernel<<<dim3(MLP/32, DIM/32, LNUM), tb>>>(w1, rw1, DIM, MLP);
    wtrans_kernel<<<dim3(DIM/32, MLP/32, LNUM), tb>>>(w2, rw2, MLP, DIM);

    cudaMemcpyAsync(out, x_in, sizeof(float)*(size_t)ROWS*DIM, cudaMemcpyDeviceToDevice);

    const __nv_bfloat16* qb = (const __nv_bfloat16*)q;
    const __nv_bfloat16* kb = (const __nv_bfloat16*)k;
    const __nv_bfloat16* vb = (const __nv_bfloat16*)v;
    const __nv_bfloat16* sb = (const __nv_bfloat16*)s;

    for (int i = 0; i < LNUM; i++) {
        // LN1 -> h (tf32, k')
        ln_kernel<<<ROWS, 256>>>(out, ln1_g + i*DIM, ln1_b + i*DIM, h);
        // QKV (tf32): h x qkvwT -> q/k/v in bf16
        gemm_tc<EPI_QKV><<<dim3(3*HID/128, ROWS/128, 1), 256>>>(
            h, rqkvw + (long)i*DIM*3*HID, qkv_b + (long)i*3*HID,
            q, k, v, 3*HID, DIM, DIM, 0, 0);
        // zero rowsums, then P = exp(q k^T) bf16, fused rowsum (bf16 MMA)
        cudaMemsetAsync(rs, 0, sizeof(float)*BH*SEQ);
        gemm_bf<EPIB_EXPSTORE><<<dim3(SEQ/128, SEQ/128, BH), 256>>>(
            qb, kb, s, rs, SEQ, DIM, (long)SEQ*DIM, (long)SEQ*DIM, (long)SEQ*SEQ);
        // o = P V / (rowsum*16) (bf16 MMA), scatter tf32
        gemm_bf<EPIB_OSCAT><<<dim3(DIM/128, SEQ/128, BH), 256>>>(
            sb, vb, o, rs, DIM, SEQ, (long)SEQ*SEQ, (long)DIM*SEQ, 0);
        // x += o @ proj_w + proj_b : split-K=4, atomic residual
        gemm_tc<EPI_BIAS_RES><<<dim3(DIM/128, ROWS/128, 4), 256>>>(
            o, rprojw + (long)i*HID*DIM, proj_b + (long)i*DIM,
            out, nullptr, nullptr, DIM, HID/4, HID, HID/4, HID/4);
        // LN2 -> h
        ln_kernel<<<ROWS, 256>>>(out, ln2_g + i*DIM, ln2_b + i*DIM, h);
        // mh = gelu(h @ w1 + b1)
        gemm_tc<EPI_BIAS_GELU><<<dim3(MLP/128, ROWS/128, 1), 256>>>(
            h, rw1 + (long)i*DIM*MLP, b1 + (long)i*MLP,
            mh, nullptr, nullptr, MLP, DIM, DIM, 0, 0);
        // x += mh @ w2 + b2 : split-K=4, atomic residual
        gemm_tc<EPI_BIAS_RES><<<dim3(DIM/128, ROWS/128, 4), 256>>>(
            mh, rw2 + (long)i*MLP*DIM, b2 + (long)i*DIM,
            out, nullptr, nullptr, DIM, MLP/4, MLP, MLP/4, MLP/4);
    }
}

// round 9
// speedup vs baseline: 2.0058x; 1.1769x over previous
#include <cuda_runtime.h>
#include <cuda_bf16.h>
#include <math.h>

#define LNUM 4
#define DIM 256
#define NH 8
#define MLP 1024
#define BATCH 8
#define SEQ 1024
#define HID 2048            // NH * DIM
#define ROWS (BATCH*SEQ)    // 8192
#define BH (BATCH*NH)       // 64

// ---------------- scratch (device globals; no allocation allowed) ----------------
__device__ __nv_bfloat16 g_h[ROWS*DIM];              // LN output
__device__ __nv_bfloat16 g_q[BH*SEQ*DIM];            // q [b,h,n,d]
__device__ __nv_bfloat16 g_k[BH*SEQ*DIM];            // k [b,h,n,d]
__device__ __nv_bfloat16 g_v[BH*DIM*SEQ];            // v TRANSPOSED [b,h,d,n]
__device__ __nv_bfloat16 g_s[(size_t)BH*SEQ*SEQ];    // exp(scores) [bh][q][k]
__device__ float         g_rs[BH*SEQ];               // attention row sums
__device__ __nv_bfloat16 g_o[(size_t)ROWS*HID];      // attn out [b,n,h*d]
__device__ __nv_bfloat16 g_m[ROWS*MLP];              // mlp hidden
// transposed bf16 weights: [N][K]
__device__ __nv_bfloat16 g_qkvw[LNUM*DIM*3*HID];
__device__ __nv_bfloat16 g_projw[LNUM*HID*DIM];
__device__ __nv_bfloat16 g_w1[LNUM*DIM*MLP];
__device__ __nv_bfloat16 g_w2[LNUM*MLP*DIM];

// ---------------- weight preprocess: transpose [K][N] -> [N][K], cvt bf16 -------
__global__ void wtrans_kernel(const float* __restrict__ src, __nv_bfloat16* __restrict__ dst,
                              int K, int N)
{
    __shared__ float tile[32][33];
    long zo = (long)blockIdx.z * K * N;
    int k0 = blockIdx.y * 32, n0 = blockIdx.x * 32;
    for (int i = threadIdx.y; i < 32; i += 8)
        tile[i][threadIdx.x] = src[zo + (long)(k0 + i)*N + n0 + threadIdx.x];
    __syncthreads();
    int k = k0 + threadIdx.x;
    for (int i = threadIdx.y; i < 32; i += 8)
        dst[zo + (long)(n0 + i)*K + k] = __float2bfloat16(tile[threadIdx.x][i]);
}

// ---------------- LayerNorm: one block (256 thr) per row; writes bf16 -----------
__global__ void ln_kernel(const float* __restrict__ x, const float* __restrict__ g,
                          const float* __restrict__ b, __nv_bfloat16* __restrict__ out)
{
    __shared__ float red0[8], red1[8];
    __shared__ float mv0, mv1;
    int row = blockIdx.x;
    int t = threadIdx.x;
    float val = x[(long)row*DIM + t];
    float s1 = val, s2 = val*val;
    #pragma unroll
    for (int o = 16; o > 0; o >>= 1) {
        s1 += __shfl_xor_sync(0xffffffffu, s1, o);
        s2 += __shfl_xor_sync(0xffffffffu, s2, o);
    }
    if ((t & 31) == 0) { red0[t>>5] = s1; red1[t>>5] = s2; }
    __syncthreads();
    if (t == 0) {
        float a = 0.f, c = 0.f;
        #pragma unroll
        for (int i = 0; i < 8; i++) { a += red0[i]; c += red1[i]; }
        float m = a * (1.0f/DIM);
        mv0 = m;
        mv1 = rsqrtf(c * (1.0f/DIM) - m*m + 1e-5f);
    }
    __syncthreads();
    out[(long)row*DIM + t] = __float2bfloat16((val - mv0) * mv1 * g[t] + b[t]);
}

// ---------------- MMA / cp.async helpers ----------------
__device__ __forceinline__ void mma_bf16(float* d, unsigned a0, unsigned a1, unsigned a2,
                                         unsigned a3, unsigned b0, unsigned b1) {
    asm volatile(
        "mma.sync.aligned.m16n8k16.row.col.f32.bf16.bf16.f32 "
        "{%0,%1,%2,%3}, {%4,%5,%6,%7}, {%8,%9}, {%0,%1,%2,%3};"
        : "+f"(d[0]), "+f"(d[1]), "+f"(d[2]), "+f"(d[3])
        : "r"(a0), "r"(a1), "r"(a2), "r"(a3), "r"(b0), "r"(b1));
}
__device__ __forceinline__ void cpa16(unsigned d, const void* s) {
    asm volatile("cp.async.ca.shared.global [%0], [%1], 16;" :: "r"(d), "l"(s));
}

// ================================================================================
// Unified bf16 TC GEMM: C[m][n] = sum_k A[m][k] B[n][k], both operands [rows][K] bf16.
// Block 128x128, 256 thr, warp 32x64, m16n8k16, cp.async double-buffered.
// ldk = operand row stride; z-dim: batch (sA/sB/sC strides) or split-K chunk.
// ================================================================================
enum { EPI_QKV = 0, EPI_EXPSTORE = 1, EPI_OSCAT = 2, EPI_RES = 3, EPI_GELU = 4 };

#define BKS 80             // bytes per staged row (64B data + 16B pad): conflict-free
#define BTSZ (128*BKS)

template<int EPI>
__global__ __launch_bounds__(256, 2)
void gemm_bf(const __nv_bfloat16* __restrict__ A, const __nv_bfloat16* __restrict__ Bm,
             const float* __restrict__ bias, void* __restrict__ Cp,
             void* __restrict__ P1, void* __restrict__ P2, float* __restrict__ RS,
             int Nc, int K, int ldk, long sA, long sB, long sC)
{
    __shared__ char As[2][BTSZ];
    __shared__ char Bs[2][BTSZ];

    int z  = blockIdx.z;
    int m0 = blockIdx.y * 128;
    int n0 = blockIdx.x * 128;
    int t    = threadIdx.x;
    int lane = t & 31;
    int warp = t >> 5;
    int wm = (warp >> 1) * 32;
    int wn = (warp & 1) * 64;
    int gid = lane >> 2;
    int tig = lane & 3;

    // loader: 128 rows x 64B per operand per iter; 2 threads/row, 32B each
    int lr = t >> 1;
    const __nv_bfloat16* apg = A + z*sA + (long)(m0 + lr)*ldk + (t & 1)*16;
    const __nv_bfloat16* bpg = Bm + z*sB + (long)(n0 + lr)*ldk + (t & 1)*16;
    unsigned asb = (unsigned)__cvta_generic_to_shared(&As[0][0]);
    unsigned bsb = (unsigned)__cvta_generic_to_shared(&Bs[0][0]);
    unsigned ad0 = asb + (unsigned)(lr*BKS + (t & 1)*32);
    unsigned bd0 = bsb + (unsigned)(lr*BKS + (t & 1)*32);

    float acc[2][8][4];
    #pragma unroll
    for (int mt = 0; mt < 2; mt++)
        #pragma unroll
        for (int nt = 0; nt < 8; nt++)
            #pragma unroll
            for (int p = 0; p < 4; p++) acc[mt][nt][p] = 0.f;

    cpa16(ad0, apg);  cpa16(ad0 + 16, apg + 8);
    cpa16(bd0, bpg);  cpa16(bd0 + 16, bpg + 8);
    asm volatile("cp.async.commit_group;");

    int niter = K / 32;
    for (int iter = 0; iter < niter; iter++) {
        int s = iter & 1;
        if (iter + 1 < niter) {
            int k0 = (iter + 1) * 32;
            unsigned ad = ad0 + (unsigned)((s^1)*BTSZ);
            unsigned bd = bd0 + (unsigned)((s^1)*BTSZ);
            cpa16(ad, apg + k0);  cpa16(ad + 16, apg + k0 + 8);
            cpa16(bd, bpg + k0);  cpa16(bd + 16, bpg + k0 + 8);
            asm volatile("cp.async.commit_group;");
            asm volatile("cp.async.wait_group 1;");
        } else {
            asm volatile("cp.async.wait_group 0;");
        }
        __syncthreads();

        const char* Ab_ = &As[s][0];
        const char* Bb_ = &Bs[s][0];
        #pragma unroll
        for (int kkb = 0; kkb < 64; kkb += 32) {   // two k16 halves (32B each)
            unsigned af[2][4], bf[8][2];
            #pragma unroll
            for (int mt = 0; mt < 2; mt++) {
                int r = wm + mt*16 + gid;
                const char* pa = Ab_ + r*BKS + kkb + 4*tig;
                const char* pa8 = Ab_ + (r+8)*BKS + kkb + 4*tig;
                af[mt][0] = *(const unsigned*)pa;
                af[mt][1] = *(const unsigned*)pa8;
                af[mt][2] = *(const unsigned*)(pa + 16);
                af[mt][3] = *(const unsigned*)(pa8 + 16);
            }
            #pragma unroll
            for (int nt = 0; nt < 8; nt++) {
                int c = wn + nt*8 + gid;
                const char* pb = Bb_ + c*BKS + kkb + 4*tig;
                bf[nt][0] = *(const unsigned*)pb;
                bf[nt][1] = *(const unsigned*)(pb + 16);
            }
            #pragma unroll
            for (int mt = 0; mt < 2; mt++)
                #pragma unroll
                for (int nt = 0; nt < 8; nt++)
                    mma_bf16(acc[mt][nt], af[mt][0], af[mt][1], af[mt][2], af[mt][3],
                             bf[nt][0], bf[nt][1]);
        }
        __syncthreads();
    }

    // ---------------- epilogues ----------------
    if (EPI == EPI_EXPSTORE) {
        __nv_bfloat16* Pb = (__nv_bfloat16*)Cp;
        float ls[2][2] = {{0.f, 0.f}, {0.f, 0.f}};
        #pragma unroll
        for (int mt = 0; mt < 2; mt++) {
            int r = m0 + wm + mt*16 + gid;
            #pragma unroll
            for (int nt = 0; nt < 8; nt++) {
                int c = n0 + wn + nt*8 + 2*tig;
                float e0 = expf(acc[mt][nt][0]);
                float e1 = expf(acc[mt][nt][1]);
                float e2 = expf(acc[mt][nt][2]);
                float e3 = expf(acc[mt][nt][3]);
                __nv_bfloat162 lo, hi;
                lo.x = __float2bfloat16(e0); lo.y = __float2bfloat16(e1);
                hi.x = __float2bfloat16(e2); hi.y = __float2bfloat16(e3);
                *(__nv_bfloat162*)&Pb[(long)z*sC + (long)r*Nc + c]     = lo;
                *(__nv_bfloat162*)&Pb[(long)z*sC + (long)(r+8)*Nc + c] = hi;
                ls[mt][0] += e0 + e1;
                ls[mt][1] += e2 + e3;
            }
        }
        #pragma unroll
        for (int mt = 0; mt < 2; mt++)
            #pragma unroll
            for (int hlf = 0; hlf < 2; hlf++) {
                float v = ls[mt][hlf];
                v += __shfl_xor_sync(0xffffffffu, v, 1);
                v += __shfl_xor_sync(0xffffffffu, v, 2);
                if (tig == 0) {
                    int row = m0 + wm + mt*16 + gid + hlf*8;
                    atomicAdd(&RS[(long)z*SEQ + row], v);
                }
            }
        return;
    }

    #pragma unroll
    for (int mt = 0; mt < 2; mt++) {
        #pragma unroll
        for (int nt = 0; nt < 8; nt++) {
            #pragma unroll
            for (int p = 0; p < 4; p++) {
                int row = m0 + wm + mt*16 + gid + ((p >= 2) ? 8 : 0);
                int col = n0 + wn + nt*8 + 2*tig + (p & 1);
                float v = acc[mt][nt][p];
                if (EPI == EPI_QKV) {
                    v += bias[col];
                    int si = col % 3;
                    int dc = (col / 3) & (DIM - 1);
                    int h  = col / (3*DIM);
                    int b  = row >> 10, n = row & (SEQ - 1);
                    long bh = b*NH + h;
                    if (si == 2) {       // v transposed [b,h,d,n]
                        ((__nv_bfloat16*)P2)[(bh*DIM + dc)*SEQ + n] = __float2bfloat16(v);
                    } else {             // q/k [b,h,n,d]
                        __nv_bfloat16* dst = (__nv_bfloat16*)((si == 0) ? Cp : P1);
                        dst[(bh*SEQ + n)*DIM + dc] = __float2bfloat16(v);
                    }
                } else if (EPI == EPI_RES) {      // split-K residual: fp32 atomic
                    float add = v + ((z == 0) ? bias[col] : 0.f);
                    atomicAdd(&((float*)Cp)[(long)row*Nc + col], add);
                } else if (EPI == EPI_GELU) {     // mh bf16
                    float u = v + bias[col];
                    ((__nv_bfloat16*)Cp)[(long)row*Nc + col] =
                        __float2bfloat16(0.5f * u * (1.0f + erff(u * 0.70710678118654752f)));
                } else {                          // EPI_OSCAT: normalize + scatter bf16
                    int b = z >> 3, h = z & 7;
                    float inv = 1.0f / (RS[(long)z*SEQ + row] * 16.0f);
                    ((__nv_bfloat16*)Cp)[((long)(b*SEQ + row))*HID + h*DIM + col] =
                        __float2bfloat16(v * inv);
                }
            }
        }
    }
}

// ---------------- host orchestration ----------------
extern "C" void kernel_launch(void* const* d_in, const int* in_sizes, int n_in,
                              void* d_out, int out_size)
{
    const float* x_in  = (const float*)d_in[0];
    const float* ln1_g = (const float*)d_in[1];
    const float* ln1_b = (const float*)d_in[2];
    const float* qkv_w = (const float*)d_in[3];
    const float* qkv_b = (const float*)d_in[4];
    const float* proj_w= (const float*)d_in[5];
    const float* proj_b= (const float*)d_in[6];
    const float* ln2_g = (const float*)d_in[7];
    const float* ln2_b = (const float*)d_in[8];
    const float* w1    = (const float*)d_in[9];
    const float* b1    = (const float*)d_in[10];
    const float* w2    = (const float*)d_in[11];
    const float* b2    = (const float*)d_in[12];
    float* out = (float*)d_out;

    __nv_bfloat16 *h, *q, *k, *v, *s, *o, *mh, *rqkvw, *rprojw, *rw1, *rw2;
    float *rs;
    cudaGetSymbolAddress((void**)&h,  g_h);
    cudaGetSymbolAddress((void**)&q,  g_q);
    cudaGetSymbolAddress((void**)&k,  g_k);
    cudaGetSymbolAddress((void**)&v,  g_v);
    cudaGetSymbolAddress((void**)&s,  g_s);
    cudaGetSymbolAddress((void**)&rs, g_rs);
    cudaGetSymbolAddress((void**)&o,  g_o);
    cudaGetSymbolAddress((void**)&mh, g_m);
    cudaGetSymbolAddress((void**)&rqkvw, g_qkvw);
    cudaGetSymbolAddress((void**)&rprojw, g_projw);
    cudaGetSymbolAddress((void**)&rw1, g_w1);
    cudaGetSymbolAddress((void**)&rw2, g_w2);

    // preprocess weights: transpose to [N][K], convert bf16
    dim3 tb(32, 8);
    wtrans_kernel<<<dim3(3*HID/32, DIM/32, LNUM), tb>>>(qkv_w,  rqkvw,  DIM, 3*HID);
    wtrans_kernel<<<dim3(DIM/32, HID/32, LNUM), tb>>>(proj_w, rprojw, HID, DIM);
    wtrans_kernel<<<dim3(MLP/32, DIM/32, LNUM), tb>>>(w1, rw1, DIM, MLP);
    wtrans_kernel<<<dim3(DIM/32, MLP/32, LNUM), tb>>>(w2, rw2, MLP, DIM);

    cudaMemcpyAsync(out, x_in, sizeof(float)*(size_t)ROWS*DIM, cudaMemcpyDeviceToDevice);

    for (int i = 0; i < LNUM; i++) {
        // LN1 -> h bf16
        ln_kernel<<<ROWS, 256>>>(out, ln1_g + i*DIM, ln1_b + i*DIM, h);
        // QKV: h [8192][256] x qkvwT [6144][256] -> scatter q/k/v bf16
        gemm_bf<EPI_QKV><<<dim3(3*HID/128, ROWS/128, 1), 256>>>(
            h, rqkvw + (long)i*DIM*3*HID, qkv_b + (long)i*3*HID,
            q, k, v, nullptr, 3*HID, DIM, DIM, 0, 0, 0);
        // P = exp(q k^T) bf16 with fused rowsum
        cudaMemsetAsync(rs, 0, sizeof(float)*BH*SEQ);
        gemm_bf<EPI_EXPSTORE><<<dim3(SEQ/128, SEQ/128, BH), 256>>>(
            q, k, nullptr, s, nullptr, nullptr, rs,
            SEQ, DIM, DIM, (long)SEQ*DIM, (long)SEQ*DIM, (long)SEQ*SEQ);
        // o = P V / (rowsum*16), scatter bf16 [b,n,h*d]
        gemm_bf<EPI_OSCAT><<<dim3(DIM/128, SEQ/128, BH), 256>>>(
            s, v, nullptr, o, nullptr, nullptr, rs,
            DIM, SEQ, SEQ, (long)SEQ*SEQ, (long)DIM*SEQ, 0);
        // x += o @ proj_w + proj_b : split-K=4, fp32 atomic residual
        gemm_bf<EPI_RES><<<dim3(DIM/128, ROWS/128, 4), 256>>>(
            o, rprojw + (long)i*HID*DIM, proj_b + (long)i*DIM,
            out, nullptr, nullptr, nullptr, DIM, HID/4, HID, HID/4, HID/4, 0);
        // LN2 -> h bf16
        ln_kernel<<<ROWS, 256>>>(out, ln2_g + i*DIM, ln2_b + i*DIM, h);
        // mh = gelu(h @ w1 + b1) bf16
        gemm_bf<EPI_GELU><<<dim3(MLP/128, ROWS/128, 1), 256>>>(
            h, rw1 + (long)i*DIM*MLP, b1 + (long)i*MLP,
            mh, nullptr, nullptr, nullptr, MLP, DIM, DIM, 0, 0, 0);
        // x += mh @ w2 + b2 : split-K=4, fp32 atomic residual
        gemm_bf<EPI_RES><<<dim3(DIM/128, ROWS/128, 4), 256>>>(
            mh, rw2 + (long)i*MLP*DIM, b2 + (long)i*DIM,
            out, nullptr, nullptr, nullptr, DIM, MLP/4, MLP, MLP/4, MLP/4, 0);
    }
}

// round 10
// speedup vs baseline: 2.2759x; 1.1346x over previous
#include <cuda_runtime.h>
#include <cuda_bf16.h>
#include <math.h>

#define LNUM 4
#define DIM 256
#define NH 8
#define MLP 1024
#define BATCH 8
#define SEQ 1024
#define HID 2048            // NH * DIM
#define ROWS (BATCH*SEQ)    // 8192
#define BH (BATCH*NH)       // 64

// ---------------- scratch (device globals; no allocation allowed) ----------------
__device__ __nv_bfloat16 g_h[ROWS*DIM];              // LN output
__device__ __nv_bfloat16 g_q[BH*SEQ*DIM];            // q [b,h,n,d]
__device__ __nv_bfloat16 g_k[BH*SEQ*DIM];            // k [b,h,n,d]
__device__ __nv_bfloat16 g_v[BH*DIM*SEQ];            // v TRANSPOSED [b,h,d,n]
__device__ __nv_bfloat16 g_s[(size_t)BH*SEQ*SEQ];    // exp(scores) [bh][q][k]
__device__ float         g_rs[BH*SEQ];               // attention row sums
__device__ __nv_bfloat16 g_o[(size_t)ROWS*HID];      // attn out [b,n,h*d]
__device__ __nv_bfloat16 g_m[ROWS*MLP];              // mlp hidden
// transposed bf16 weights: [N][K]
__device__ __nv_bfloat16 g_qkvw[LNUM*DIM*3*HID];
__device__ __nv_bfloat16 g_projw[LNUM*HID*DIM];
__device__ __nv_bfloat16 g_w1[LNUM*DIM*MLP];
__device__ __nv_bfloat16 g_w2[LNUM*MLP*DIM];

// ---------------- weight preprocess: transpose [K][N] -> [N][K], cvt bf16 -------
__global__ void wtrans_kernel(const float* __restrict__ src, __nv_bfloat16* __restrict__ dst,
                              int K, int N)
{
    __shared__ float tile[32][33];
    long zo = (long)blockIdx.z * K * N;
    int k0 = blockIdx.y * 32, n0 = blockIdx.x * 32;
    for (int i = threadIdx.y; i < 32; i += 8)
        tile[i][threadIdx.x] = src[zo + (long)(k0 + i)*N + n0 + threadIdx.x];
    __syncthreads();
    int k = k0 + threadIdx.x;
    for (int i = threadIdx.y; i < 32; i += 8)
        dst[zo + (long)(n0 + i)*K + k] = __float2bfloat16(tile[threadIdx.x][i]);
}

// ---------------- LayerNorm: one block (256 thr) per row; writes bf16 -----------
__global__ void ln_kernel(const float* __restrict__ x, const float* __restrict__ g,
                          const float* __restrict__ b, __nv_bfloat16* __restrict__ out)
{
    __shared__ float red0[8], red1[8];
    __shared__ float mv0, mv1;
    int row = blockIdx.x;
    int t = threadIdx.x;
    float val = x[(long)row*DIM + t];
    float s1 = val, s2 = val*val;
    #pragma unroll
    for (int o = 16; o > 0; o >>= 1) {
        s1 += __shfl_xor_sync(0xffffffffu, s1, o);
        s2 += __shfl_xor_sync(0xffffffffu, s2, o);
    }
    if ((t & 31) == 0) { red0[t>>5] = s1; red1[t>>5] = s2; }
    __syncthreads();
    if (t == 0) {
        float a = 0.f, c = 0.f;
        #pragma unroll
        for (int i = 0; i < 8; i++) { a += red0[i]; c += red1[i]; }
        float m = a * (1.0f/DIM);
        mv0 = m;
        mv1 = rsqrtf(c * (1.0f/DIM) - m*m + 1e-5f);
    }
    __syncthreads();
    out[(long)row*DIM + t] = __float2bfloat16((val - mv0) * mv1 * g[t] + b[t]);
}

// ---------------- MMA / cp.async / ldmatrix helpers ----------------
__device__ __forceinline__ void mma_bf16(float* d, unsigned a0, unsigned a1, unsigned a2,
                                         unsigned a3, unsigned b0, unsigned b1) {
    asm volatile(
        "mma.sync.aligned.m16n8k16.row.col.f32.bf16.bf16.f32 "
        "{%0,%1,%2,%3}, {%4,%5,%6,%7}, {%8,%9}, {%0,%1,%2,%3};"
        : "+f"(d[0]), "+f"(d[1]), "+f"(d[2]), "+f"(d[3])
        : "r"(a0), "r"(a1), "r"(a2), "r"(a3), "r"(b0), "r"(b1));
}
__device__ __forceinline__ void cpa16(unsigned d, const void* s) {
    asm volatile("cp.async.ca.shared.global [%0], [%1], 16;" :: "r"(d), "l"(s));
}
__device__ __forceinline__ void ldsm_x4(unsigned* r, unsigned a) {
    asm volatile("ldmatrix.sync.aligned.m8n8.x4.shared.b16 {%0,%1,%2,%3}, [%4];"
        : "=r"(r[0]), "=r"(r[1]), "=r"(r[2]), "=r"(r[3]) : "r"(a));
}

// ================================================================================
// Unified bf16 TC GEMM: C[m][n] = sum_k A[m][k] B[n][k], operands [rows][K] bf16.
// Block 128x128, 256 thr, warp 32x64, m16n8k16.
// 3-stage cp.async pipeline, ONE __syncthreads per 32-k iter, ldmatrix fragments.
// ================================================================================
enum { EPI_QKV = 0, EPI_EXPSTORE = 1, EPI_OSCAT = 2, EPI_RES = 3, EPI_GELU = 4 };

#define BKS 80             // bytes per staged row (64B data + 16B pad): LDSM conflict-free
#define ASTG (128*BKS)     // one stage of one operand (10240 B)
#define NSTG 3
#define GSMEM (2*NSTG*ASTG)   // 61440 B dynamic smem

template<int EPI>
__global__ __launch_bounds__(256, 2)
void gemm_bf(const __nv_bfloat16* __restrict__ A, const __nv_bfloat16* __restrict__ Bm,
             const float* __restrict__ bias, void* __restrict__ Cp,
             void* __restrict__ P1, void* __restrict__ P2, float* __restrict__ RS,
             int Nc, int K, int ldk, long sA, long sB, long sC)
{
    extern __shared__ char dsm[];

    int z  = blockIdx.z;
    int m0 = blockIdx.y * 128;
    int n0 = blockIdx.x * 128;
    int t    = threadIdx.x;
    int lane = t & 31;
    int warp = t >> 5;
    int wm = (warp >> 1) * 32;
    int wn = (warp & 1) * 64;
    int gid = lane >> 2;
    int tig = lane & 3;

    // loader: 128 rows x 64B per operand per iter; 2 threads/row, 32B each
    int lr = t >> 1;
    const __nv_bfloat16* apg = A + z*sA + (long)(m0 + lr)*ldk + (t & 1)*16;
    const __nv_bfloat16* bpg = Bm + z*sB + (long)(n0 + lr)*ldk + (t & 1)*16;
    unsigned asb = (unsigned)__cvta_generic_to_shared(dsm);
    unsigned bsb = asb + NSTG*ASTG;
    unsigned adl = asb + (unsigned)(lr*BKS + (t & 1)*32);
    unsigned bdl = bsb + (unsigned)(lr*BKS + (t & 1)*32);

    // ldmatrix per-lane row offset: matrix id m = lane>>3, sub-row = lane&7
    int lm = lane >> 3, ls = lane & 7;
    unsigned lro = (unsigned)(((lm & 1)*8 + ls)*BKS + (lm >> 1)*16);
    unsigned abase = asb + (unsigned)(wm*BKS) + lro;
    unsigned bbase = bsb + (unsigned)(wn*BKS) + lro;

    float acc[2][8][4];
    #pragma unroll
    for (int mt = 0; mt < 2; mt++)
        #pragma unroll
        for (int nt = 0; nt < 8; nt++)
            #pragma unroll
            for (int p = 0; p < 4; p++) acc[mt][nt][p] = 0.f;

    int niter = K / 32;
    // prologue: stages 0 and 1
    #pragma unroll
    for (int pi = 0; pi < 2; pi++) {
        int k0 = pi * 32;
        unsigned ao = (unsigned)(pi*ASTG);
        cpa16(adl + ao, apg + k0);  cpa16(adl + ao + 16, apg + k0 + 8);
        cpa16(bdl + ao, bpg + k0);  cpa16(bdl + ao + 16, bpg + k0 + 8);
        asm volatile("cp.async.commit_group;");
    }

    int st = 0;                  // stage of current iter
    for (int iter = 0; iter < niter; iter++) {
        if (iter + 1 < niter) asm volatile("cp.async.wait_group 1;");
        else                  asm volatile("cp.async.wait_group 0;");
        __syncthreads();

        if (iter + 2 < niter) {
            int k0 = (iter + 2) * 32;
            int ws = st + 2; if (ws >= NSTG) ws -= NSTG;
            unsigned ao = (unsigned)(ws*ASTG);
            cpa16(adl + ao, apg + k0);  cpa16(adl + ao + 16, apg + k0 + 8);
            cpa16(bdl + ao, bpg + k0);  cpa16(bdl + ao + 16, bpg + k0 + 8);
            asm volatile("cp.async.commit_group;");
        }

        unsigned so = (unsigned)(st*ASTG);
        #pragma unroll
        for (int kh = 0; kh < 2; kh++) {      // two k16 halves, byte offset kh*32
            unsigned af[2][4], bq[4][4];
            #pragma unroll
            for (int mt = 0; mt < 2; mt++)
                ldsm_x4(af[mt], abase + so + (unsigned)(mt*16*BKS + kh*32));
            #pragma unroll
            for (int p = 0; p < 4; p++)
                ldsm_x4(bq[p], bbase + so + (unsigned)(p*16*BKS + kh*32));
            #pragma unroll
            for (int mt = 0; mt < 2; mt++)
                #pragma unroll
                for (int p = 0; p < 4; p++) {
                    mma_bf16(acc[mt][2*p],   af[mt][0], af[mt][1], af[mt][2], af[mt][3],
                             bq[p][0], bq[p][2]);
                    mma_bf16(acc[mt][2*p+1], af[mt][0], af[mt][1], af[mt][2], af[mt][3],
                             bq[p][1], bq[p][3]);
                }
        }
        st++; if (st >= NSTG) st = 0;
    }

    // ---------------- epilogues (unchanged from R9) ----------------
    if (EPI == EPI_EXPSTORE) {
        __nv_bfloat16* Pb = (__nv_bfloat16*)Cp;
        float ls2[2][2] = {{0.f, 0.f}, {0.f, 0.f}};
        #pragma unroll
        for (int mt = 0; mt < 2; mt++) {
            int r = m0 + wm + mt*16 + gid;
            #pragma unroll
            for (int nt = 0; nt < 8; nt++) {
                int c = n0 + wn + nt*8 + 2*tig;
                float e0 = expf(acc[mt][nt][0]);
                float e1 = expf(acc[mt][nt][1]);
                float e2 = expf(acc[mt][nt][2]);
                float e3 = expf(acc[mt][nt][3]);
                __nv_bfloat162 lo, hi;
                lo.x = __float2bfloat16(e0); lo.y = __float2bfloat16(e1);
                hi.x = __float2bfloat16(e2); hi.y = __float2bfloat16(e3);
                *(__nv_bfloat162*)&Pb[(long)z*sC + (long)r*Nc + c]     = lo;
                *(__nv_bfloat162*)&Pb[(long)z*sC + (long)(r+8)*Nc + c] = hi;
                ls2[mt][0] += e0 + e1;
                ls2[mt][1] += e2 + e3;
            }
        }
        #pragma unroll
        for (int mt = 0; mt < 2; mt++)
            #pragma unroll
            for (int hlf = 0; hlf < 2; hlf++) {
                float v = ls2[mt][hlf];
                v += __shfl_xor_sync(0xffffffffu, v, 1);
                v += __shfl_xor_sync(0xffffffffu, v, 2);
                if (tig == 0) {
                    int row = m0 + wm + mt*16 + gid + hlf*8;
                    atomicAdd(&RS[(long)z*SEQ + row], v);
                }
            }
        return;
    }

    #pragma unroll
    for (int mt = 0; mt < 2; mt++) {
        #pragma unroll
        for (int nt = 0; nt < 8; nt++) {
            #pragma unroll
            for (int p = 0; p < 4; p++) {
                int row = m0 + wm + mt*16 + gid + ((p >= 2) ? 8 : 0);
                int col = n0 + wn + nt*8 + 2*tig + (p & 1);
                float v = acc[mt][nt][p];
                if (EPI == EPI_QKV) {
                    v += bias[col];
                    int si = col % 3;
                    int dc = (col / 3) & (DIM - 1);
                    int h  = col / (3*DIM);
                    int b  = row >> 10, n = row & (SEQ - 1);
                    long bh = b*NH + h;
                    if (si == 2) {       // v transposed [b,h,d,n]
                        ((__nv_bfloat16*)P2)[(bh*DIM + dc)*SEQ + n] = __float2bfloat16(v);
                    } else {             // q/k [b,h,n,d]
                        __nv_bfloat16* dst = (__nv_bfloat16*)((si == 0) ? Cp : P1);
                        dst[(bh*SEQ + n)*DIM + dc] = __float2bfloat16(v);
                    }
                } else if (EPI == EPI_RES) {      // split-K residual: fp32 atomic
                    float add = v + ((z == 0) ? bias[col] : 0.f);
                    atomicAdd(&((float*)Cp)[(long)row*Nc + col], add);
                } else if (EPI == EPI_GELU) {     // mh bf16
                    float u = v + bias[col];
                    ((__nv_bfloat16*)Cp)[(long)row*Nc + col] =
                        __float2bfloat16(0.5f * u * (1.0f + erff(u * 0.70710678118654752f)));
                } else {                          // EPI_OSCAT: normalize + scatter bf16
                    int b = z >> 3, h = z & 7;
                    float inv = 1.0f / (RS[(long)z*SEQ + row] * 16.0f);
                    ((__nv_bfloat16*)Cp)[((long)(b*SEQ + row))*HID + h*DIM + col] =
                        __float2bfloat16(v * inv);
                }
            }
        }
    }
}

// ---------------- host orchestration ----------------
extern "C" void kernel_launch(void* const* d_in, const int* in_sizes, int n_in,
                              void* d_out, int out_size)
{
    const float* x_in  = (const float*)d_in[0];
    const float* ln1_g = (const float*)d_in[1];
    const float* ln1_b = (const float*)d_in[2];
    const float* qkv_w = (const float*)d_in[3];
    const float* qkv_b = (const float*)d_in[4];
    const float* proj_w= (const float*)d_in[5];
    const float* proj_b= (const float*)d_in[6];
    const float* ln2_g = (const float*)d_in[7];
    const float* ln2_b = (const float*)d_in[8];
    const float* w1    = (const float*)d_in[9];
    const float* b1    = (const float*)d_in[10];
    const float* w2    = (const float*)d_in[11];
    const float* b2    = (const float*)d_in[12];
    float* out = (float*)d_out;

    __nv_bfloat16 *h, *q, *k, *v, *s, *o, *mh, *rqkvw, *rprojw, *rw1, *rw2;
    float *rs;
    cudaGetSymbolAddress((void**)&h,  g_h);
    cudaGetSymbolAddress((void**)&q,  g_q);
    cudaGetSymbolAddress((void**)&k,  g_k);
    cudaGetSymbolAddress((void**)&v,  g_v);
    cudaGetSymbolAddress((void**)&s,  g_s);
    cudaGetSymbolAddress((void**)&rs, g_rs);
    cudaGetSymbolAddress((void**)&o,  g_o);
    cudaGetSymbolAddress((void**)&mh, g_m);
    cudaGetSymbolAddress((void**)&rqkvw, g_qkvw);
    cudaGetSymbolAddress((void**)&rprojw, g_projw);
    cudaGetSymbolAddress((void**)&rw1, g_w1);
    cudaGetSymbolAddress((void**)&rw2, g_w2);

    // allow 60 KB dynamic smem per instantiation (once per process; cheap)
    cudaFuncSetAttribute(gemm_bf<EPI_QKV>,      cudaFuncAttributeMaxDynamicSharedMemorySize, GSMEM);
    cudaFuncSetAttribute(gemm_bf<EPI_EXPSTORE>, cudaFuncAttributeMaxDynamicSharedMemorySize, GSMEM);
    cudaFuncSetAttribute(gemm_bf<EPI_OSCAT>,    cudaFuncAttributeMaxDynamicSharedMemorySize, GSMEM);
    cudaFuncSetAttribute(gemm_bf<EPI_RES>,      cudaFuncAttributeMaxDynamicSharedMemorySize, GSMEM);
    cudaFuncSetAttribute(gemm_bf<EPI_GELU>,     cudaFuncAttributeMaxDynamicSharedMemorySize, GSMEM);

    // preprocess weights: transpose to [N][K], convert bf16
    dim3 tb(32, 8);
    wtrans_kernel<<<dim3(3*HID/32, DIM/32, LNUM), tb>>>(qkv_w,  rqkvw,  DIM, 3*HID);
    wtrans_kernel<<<dim3(DIM/32, HID/32, LNUM), tb>>>(proj_w, rprojw, HID, DIM);
    wtrans_kernel<<<dim3(MLP/32, DIM/32, LNUM), tb>>>(w1, rw1, DIM, MLP);
    wtrans_kernel<<<dim3(DIM/32, MLP/32, LNUM), tb>>>(w2, rw2, MLP, DIM);

    cudaMemcpyAsync(out, x_in, sizeof(float)*(size_t)ROWS*DIM, cudaMemcpyDeviceToDevice);

    for (int i = 0; i < LNUM; i++) {
        // LN1 -> h bf16
        ln_kernel<<<ROWS, 256>>>(out, ln1_g + i*DIM, ln1_b + i*DIM, h);
        // QKV: h [8192][256] x qkvwT [6144][256] -> scatter q/k/v bf16
        gemm_bf<EPI_QKV><<<dim3(3*HID/128, ROWS/128, 1), 256, GSMEM>>>(
            h, rqkvw + (long)i*DIM*3*HID, qkv_b + (long)i*3*HID,
            q, k, v, nullptr, 3*HID, DIM, DIM, 0, 0, 0);
        // P = exp(q k^T) bf16 with fused rowsum
        cudaMemsetAsync(rs, 0, sizeof(float)*BH*SEQ);
        gemm_bf<EPI_EXPSTORE><<<dim3(SEQ/128, SEQ/128, BH), 256, GSMEM>>>(
            q, k, nullptr, s, nullptr, nullptr, rs,
            SEQ, DIM, DIM, (long)SEQ*DIM, (long)SEQ*DIM, (long)SEQ*SEQ);
        // o = P V / (rowsum*16), scatter bf16 [b,n,h*d]
        gemm_bf<EPI_OSCAT><<<dim3(DIM/128, SEQ/128, BH), 256, GSMEM>>>(
            s, v, nullptr, o, nullptr, nullptr, rs,
            DIM, SEQ, SEQ, (long)SEQ*SEQ, (long)DIM*SEQ, 0);
        // x += o @ proj_w + proj_b : split-K=4, fp32 atomic residual
        gemm_bf<EPI_RES><<<dim3(DIM/128, ROWS/128, 4), 256, GSMEM>>>(
            o, rprojw + (long)i*HID*DIM, proj_b + (long)i*DIM,
            out, nullptr, nullptr, nullptr, DIM, HID/4, HID, HID/4, HID/4, 0);
        // LN2 -> h bf16
        ln_kernel<<<ROWS, 256>>>(out, ln2_g + i*DIM, ln2_b + i*DIM, h);
        // mh = gelu(h @ w1 + b1) bf16
        gemm_bf<EPI_GELU><<<dim3(MLP/128, ROWS/128, 1), 256, GSMEM>>>(
            h, rw1 + (long)i*DIM*MLP, b1 + (long)i*MLP,
            mh, nullptr, nullptr, nullptr, MLP, DIM, DIM, 0, 0, 0);
        // x += mh @ w2 + b2 : split-K=4, fp32 atomic residual
        gemm_bf<EPI_RES><<<dim3(DIM/128, ROWS/128, 4), 256, GSMEM>>>(
            mh, rw2 + (long)i*MLP*DIM, b2 + (long)i*DIM,
            out, nullptr, nullptr, nullptr, DIM, MLP/4, MLP, MLP/4, MLP/4, 0);
    }
}